// round 6
// baseline (speedup 1.0000x reference)
#include <cuda_runtime.h>
#include <cuda_bf16.h>

#define BATCH   8192
#define HID     128
#define TT      12
#define LAYERS  10
#define G4      512      // 4*HID
#define ENCL    4096
#define NMODES  25

// ---------------- scratch (static device globals; no allocation) ----------------
__device__ float g_enc [BATCH * HID];          // 4 MB
__device__ float g_Xa  [TT * BATCH * HID];     // 48 MB
__device__ float g_Xb  [TT * BATCH * HID];     // 48 MB
__device__ float g_c   [BATCH * HID];          // 4 MB
__device__ float g_plog[BATCH * NMODES];       // ~0.8 MB

// ---------------- helpers ----------------
__device__ __forceinline__ unsigned f2tf(float x) {
    unsigned u;
    asm("cvt.rna.tf32.f32 %0, %1;" : "=r"(u) : "f"(x));
    return u;
}

__device__ __forceinline__ uint4 tf4(float4 v) {
    uint4 u;
    u.x = f2tf(v.x); u.y = f2tf(v.y); u.z = f2tf(v.z); u.w = f2tf(v.w);
    return u;
}

__device__ __forceinline__ void mma_tf32(float c[4],
                                         unsigned a0, unsigned a1, unsigned a2, unsigned a3,
                                         unsigned b0, unsigned b1) {
    asm volatile(
        "mma.sync.aligned.m16n8k8.row.col.f32.tf32.tf32.f32 "
        "{%0,%1,%2,%3}, {%4,%5,%6,%7}, {%8,%9}, {%0,%1,%2,%3};\n"
        : "+f"(c[0]), "+f"(c[1]), "+f"(c[2]), "+f"(c[3])
        : "r"(a0), "r"(a1), "r"(a2), "r"(a3), "r"(b0), "r"(b1));
}

__device__ __forceinline__ float sigf(float x) {
    return __fdividef(1.f, 1.f + __expf(-x));
}
__device__ __forceinline__ float tanh_fast(float x) {
    return __fdividef(2.f, 1.f + __expf(-2.f * x)) - 1.f;
}

// ---------------- fc_in: enc = relu(backbone @ W^T + b) ----------------
// M=8192, N=128, K=4096.  CTA: 64x128, 256 thr (8 warps, warp 16x64). KC=16.
__global__ void __launch_bounds__(256) k_fcin(const float* __restrict__ A,
                                              const float* __restrict__ W,
                                              const float* __restrict__ bias,
                                              float* __restrict__ out) {
    __shared__ unsigned As[64][20];
    __shared__ unsigned Bs[128][20];
    const int tid  = threadIdx.x;
    const int lane = tid & 31;
    const int w    = tid >> 5;
    const int wm   = w & 3;     // 4 m-tiles of 16
    const int wn   = w >> 2;    // 2 n-tiles of 64
    const int row0 = blockIdx.x * 64;
    const int g    = lane >> 2;
    const int t4   = lane & 3;

    float acc[8][4];
#pragma unroll
    for (int i = 0; i < 8; i++)
#pragma unroll
        for (int j = 0; j < 4; j++) acc[i][j] = 0.f;

    for (int kc = 0; kc < ENCL / 16; kc++) {
        const int k0 = kc * 16;
        // A tile: 64 x 16 -> 256 float4, one per thread
        {
            int m = tid >> 2, kv = tid & 3;
            float4 v = *(const float4*)(A + (size_t)(row0 + m) * ENCL + k0 + kv * 4);
            *(uint4*)&As[m][kv * 4] = tf4(v);
        }
        // B tile: 128 x 16 -> 512 float4, two per thread
#pragma unroll
        for (int i = 0; i < 2; i++) {
            int idx = tid + i * 256;
            int n = idx >> 2, kv = idx & 3;
            float4 v = *(const float4*)(W + (size_t)n * ENCL + k0 + kv * 4);
            *(uint4*)&Bs[n][kv * 4] = tf4(v);
        }
        __syncthreads();
#pragma unroll
        for (int ks = 0; ks < 2; ks++) {
            const int kb = ks * 8;
            unsigned a0 = As[wm * 16 + g][kb + t4];
            unsigned a1 = As[wm * 16 + g + 8][kb + t4];
            unsigned a2 = As[wm * 16 + g][kb + t4 + 4];
            unsigned a3 = As[wm * 16 + g + 8][kb + t4 + 4];
#pragma unroll
            for (int nt = 0; nt < 8; nt++) {
                int col = wn * 64 + nt * 8 + g;
                unsigned b0 = Bs[col][kb + t4];
                unsigned b1 = Bs[col][kb + t4 + 4];
                mma_tf32(acc[nt], a0, a1, a2, a3, b0, b1);
            }
        }
        __syncthreads();
    }
    // epilogue: bias + relu
#pragma unroll
    for (int nt = 0; nt < 8; nt++)
#pragma unroll
        for (int cr = 0; cr < 4; cr++) {
            int r   = row0 + wm * 16 + g + (cr >> 1) * 8;
            int col = wn * 64 + nt * 8 + t4 * 2 + (cr & 1);
            float v = acc[nt][cr] + bias[col];
            out[r * HID + col] = fmaxf(v, 0.f);
        }
}

// ---------------- fused LSTM step ----------------
// gates = x_t @ Wih^T + h_{t-1} @ Whh^T + bih + bhh ; then cell.
// M=8192 (tile 64 -> 128 CTAs), N=512, K=256 (or 128 when t==0). 512 thr = 16 warps.
// Warp (wm,wn): rows wm*16..+15; columns {gate*128 + wn*32 + s8*8} for gate 0..3, s8 0..3
// -> each thread owns all 4 gates of its (b,j) cells: no smem exchange for the cell.
__global__ void __launch_bounds__(512) k_step(const float* __restrict__ Xt,
                                              const float* __restrict__ Hprev,
                                              const float* __restrict__ Wih,
                                              const float* __restrict__ Whh,
                                              const float* __restrict__ bih,
                                              const float* __restrict__ bhh,
                                              float* __restrict__ Cst,
                                              float* __restrict__ Hout,
                                              int t0) {
    __shared__ unsigned Bs[512][20];
    __shared__ unsigned As[64][20];
    const int tid  = threadIdx.x;
    const int lane = tid & 31;
    const int w    = tid >> 5;
    const int wm   = w & 3;     // 4 row tiles of 16
    const int wn   = w >> 2;    // 4 j-strips of 32
    const int row0 = blockIdx.x * 64;
    const int g    = lane >> 2;
    const int t4   = lane & 3;

    float acc[4][4][4];
#pragma unroll
    for (int a = 0; a < 4; a++)
#pragma unroll
        for (int b = 0; b < 4; b++)
#pragma unroll
            for (int c = 0; c < 4; c++) acc[a][b][c] = 0.f;

    const int nch = t0 ? 8 : 16;
    for (int kc = 0; kc < nch; kc++) {
        const float* Bsrc;
        const float* Asrc;
        int k0;
        if (kc < 8) { Bsrc = Wih; Asrc = Xt;    k0 = kc * 16; }
        else        { Bsrc = Whh; Asrc = Hprev; k0 = kc * 16 - 128; }

        // A tile: 64 x 16 -> 256 float4, threads 0..255
        if (tid < 256) {
            int m = tid >> 2, kv = tid & 3;
            float4 v = *(const float4*)(Asrc + (size_t)(row0 + m) * HID + k0 + kv * 4);
            *(uint4*)&As[m][kv * 4] = tf4(v);
        }
        // B tile: 512 x 16 -> 2048 float4, four per thread
#pragma unroll
        for (int i = 0; i < 4; i++) {
            int idx = tid + i * 512;
            int n = idx >> 2, kv = idx & 3;
            float4 v = *(const float4*)(Bsrc + (size_t)n * HID + k0 + kv * 4);
            *(uint4*)&Bs[n][kv * 4] = tf4(v);
        }
        __syncthreads();
#pragma unroll
        for (int ks = 0; ks < 2; ks++) {
            const int kb = ks * 8;
            unsigned a0 = As[wm * 16 + g][kb + t4];
            unsigned a1 = As[wm * 16 + g + 8][kb + t4];
            unsigned a2 = As[wm * 16 + g][kb + t4 + 4];
            unsigned a3 = As[wm * 16 + g + 8][kb + t4 + 4];
#pragma unroll
            for (int gt = 0; gt < 4; gt++)
#pragma unroll
                for (int s8 = 0; s8 < 4; s8++) {
                    int col = gt * 128 + wn * 32 + s8 * 8 + g;
                    unsigned b0 = Bs[col][kb + t4];
                    unsigned b1 = Bs[col][kb + t4 + 4];
                    mma_tf32(acc[gt][s8], a0, a1, a2, a3, b0, b1);
                }
        }
        __syncthreads();
    }

    // LSTM cell (all 4 gates in-register per thread)
#pragma unroll
    for (int s8 = 0; s8 < 4; s8++)
#pragma unroll
        for (int crH = 0; crH < 2; crH++)
#pragma unroll
            for (int crL = 0; crL < 2; crL++) {
                int cr = crH * 2 + crL;
                int b  = row0 + wm * 16 + g + crH * 8;
                int j  = wn * 32 + s8 * 8 + t4 * 2 + crL;
                float gi = acc[0][s8][cr] + bih[j]       + bhh[j];
                float gf = acc[1][s8][cr] + bih[128 + j] + bhh[128 + j];
                float gg = acc[2][s8][cr] + bih[256 + j] + bhh[256 + j];
                float go = acc[3][s8][cr] + bih[384 + j] + bhh[384 + j];
                float cold = t0 ? 0.f : Cst[b * HID + j];
                float cn   = sigf(gf) * cold + sigf(gi) * tanh_fast(gg);
                float h    = sigf(go) * tanh_fast(cn);
                Cst [b * HID + j] = cn;
                Hout[b * HID + j] = h;
            }
}

// ---------------- fc_out: fc = Y @ W^T + b, fused scatter ----------------
// Y: [T*B, 128] (rows = t*B + b). N = 75 (padded to 80). CTA: 128 rows, 256 thr.
__global__ void __launch_bounds__(256) k_fcout(const float* __restrict__ Y,
                                               const float* __restrict__ W,
                                               const float* __restrict__ bias,
                                               float* __restrict__ pred,
                                               float* __restrict__ plog) {
    __shared__ unsigned As[128][20];
    __shared__ unsigned Bs[80][20];
    const int tid  = threadIdx.x;
    const int lane = tid & 31;
    const int wm   = tid >> 5;   // 8 warps x 16 rows
    const int row0 = blockIdx.x * 128;
    const int g    = lane >> 2;
    const int t4   = lane & 3;

    float acc[10][4];
#pragma unroll
    for (int i = 0; i < 10; i++)
#pragma unroll
        for (int j = 0; j < 4; j++) acc[i][j] = 0.f;

    for (int kc = 0; kc < 8; kc++) {
        const int k0 = kc * 16;
        // A: 128 x 16 -> 512 float4, two per thread
#pragma unroll
        for (int i = 0; i < 2; i++) {
            int idx = tid + i * 256;
            int m = idx >> 2, kv = idx & 3;
            float4 v = *(const float4*)(Y + (size_t)(row0 + m) * HID + k0 + kv * 4);
            *(uint4*)&As[m][kv * 4] = tf4(v);
        }
        // B: 80 x 16 -> 320 float4 (rows >= 75 zero-padded)
#pragma unroll
        for (int i = 0; i < 2; i++) {
            int idx = tid + i * 256;
            if (idx < 320) {
                int n = idx >> 2, kv = idx & 3;
                float4 v = make_float4(0.f, 0.f, 0.f, 0.f);
                if (n < 75) v = *(const float4*)(W + (size_t)n * HID + k0 + kv * 4);
                *(uint4*)&Bs[n][kv * 4] = tf4(v);
            }
        }
        __syncthreads();
#pragma unroll
        for (int ks = 0; ks < 2; ks++) {
            const int kb = ks * 8;
            unsigned a0 = As[wm * 16 + g][kb + t4];
            unsigned a1 = As[wm * 16 + g + 8][kb + t4];
            unsigned a2 = As[wm * 16 + g][kb + t4 + 4];
            unsigned a3 = As[wm * 16 + g + 8][kb + t4 + 4];
#pragma unroll
            for (int nt = 0; nt < 10; nt++) {
                int col = nt * 8 + g;
                unsigned b0 = Bs[col][kb + t4];
                unsigned b1 = Bs[col][kb + t4 + 4];
                mma_tf32(acc[nt], a0, a1, a2, a3, b0, b1);
            }
        }
        __syncthreads();
    }
    // scatter epilogue
#pragma unroll
    for (int nt = 0; nt < 10; nt++)
#pragma unroll
        for (int cr = 0; cr < 4; cr++) {
            int col = nt * 8 + t4 * 2 + (cr & 1);
            if (col >= 75) continue;
            int r = row0 + wm * 16 + g + (cr >> 1) * 8;
            int t = r >> 13;         // / BATCH (8192)
            int b = r & (BATCH - 1);
            float v = acc[nt][cr] + bias[col];
            if (col < 50) {
                int m = col >> 1, d = col & 1;
                pred[b * (NMODES * TT * 2) + m * (TT * 2) + t * 2 + d] = v;
            } else if (t == TT - 1) {
                plog[b * NMODES + (col - 50)] = v;
            }
        }
}

// ---------------- softmax over 25 modes ----------------
__global__ void __launch_bounds__(256) k_softmax(const float* __restrict__ plog,
                                                 float* __restrict__ out) {
    int b = blockIdx.x * blockDim.x + threadIdx.x;
    if (b >= BATCH) return;
    float v[NMODES];
    float m = -1e30f;
#pragma unroll
    for (int j = 0; j < NMODES; j++) {
        v[j] = plog[b * NMODES + j];
        m = fmaxf(m, v[j]);
    }
    float s = 0.f;
#pragma unroll
    for (int j = 0; j < NMODES; j++) {
        v[j] = __expf(v[j] - m);
        s += v[j];
    }
    float inv = __fdividef(1.f, s);
#pragma unroll
    for (int j = 0; j < NMODES; j++) out[b * NMODES + j] = v[j] * inv;
}

// ---------------- launcher ----------------
extern "C" void kernel_launch(void* const* d_in, const int* in_sizes, int n_in,
                              void* d_out, int out_size) {
    const float* backbone = (const float*)d_in[0];
    const float* fcW      = (const float*)d_in[1];
    const float* fcb      = (const float*)d_in[2];
    const float* Wih      = (const float*)d_in[3];
    const float* Whh      = (const float*)d_in[4];
    const float* bih      = (const float*)d_in[5];
    const float* bhh      = (const float*)d_in[6];
    const float* foW      = (const float*)d_in[7];
    const float* fob      = (const float*)d_in[8];

    float* out  = (float*)d_out;
    float* pred = out;
    float* prob = out + (size_t)BATCH * NMODES * TT * 2;

    float *encb, *pXa, *pXb, *cbuf, *plogb;
    cudaGetSymbolAddress((void**)&encb,  g_enc);
    cudaGetSymbolAddress((void**)&pXa,   g_Xa);
    cudaGetSymbolAddress((void**)&pXb,   g_Xb);
    cudaGetSymbolAddress((void**)&cbuf,  g_c);
    cudaGetSymbolAddress((void**)&plogb, g_plog);

    k_fcin<<<BATCH / 64, 256>>>(backbone, fcW, fcb, encb);

    const float* Xin = encb;
    bool  layer0 = true;
    float* Xout = pXa;
    for (int l = 0; l < LAYERS; l++) {
        const float* Wl  = Wih + (size_t)l * G4 * HID;
        const float* Ul  = Whh + (size_t)l * G4 * HID;
        const float* bl  = bih + (size_t)l * G4;
        const float* b2l = bhh + (size_t)l * G4;
        for (int t = 0; t < TT; t++) {
            const float* xt = layer0 ? encb : (Xin + (size_t)t * BATCH * HID);
            const float* hp = (t == 0) ? encb /*unused*/ : (Xout + (size_t)(t - 1) * BATCH * HID);
            k_step<<<BATCH / 64, 512>>>(xt, hp, Wl, Ul, bl, b2l, cbuf,
                                        Xout + (size_t)t * BATCH * HID, t == 0 ? 1 : 0);
        }
        Xin   = Xout;
        layer0 = false;
        Xout  = (Xout == pXa) ? pXb : pXa;
    }

    k_fcout<<<(TT * BATCH) / 128, 256>>>(Xin, foW, fob, pred, plogb);
    k_softmax<<<BATCH / 256, 256>>>(plogb, prob);
}

// round 7
// speedup vs baseline: 1.0044x; 1.0044x over previous
#include <cuda_runtime.h>
#include <cuda_bf16.h>

#define BATCH   8192
#define HID     128
#define TT      12
#define LAYERS  10
#define G4      512      // 4*HID
#define ENCL    4096
#define NMODES  25

// ---------------- scratch (static device globals; no allocation) ----------------
__device__ float g_enc [BATCH * HID];          // 4 MB
__device__ float g_Xa  [TT * BATCH * HID];     // 48 MB
__device__ float g_Xb  [TT * BATCH * HID];     // 48 MB
__device__ float g_c   [BATCH * HID];          // 4 MB
__device__ float g_plog[BATCH * NMODES];       // ~0.8 MB

// ---------------- helpers ----------------
__device__ __forceinline__ unsigned f2tf(float x) {
    unsigned u;
    asm("cvt.rna.tf32.f32 %0, %1;" : "=r"(u) : "f"(x));
    return u;
}

__device__ __forceinline__ uint4 tf4(float4 v) {
    uint4 u;
    u.x = f2tf(v.x); u.y = f2tf(v.y); u.z = f2tf(v.z); u.w = f2tf(v.w);
    return u;
}

__device__ __forceinline__ void mma_tf32(float c[4],
                                         unsigned a0, unsigned a1, unsigned a2, unsigned a3,
                                         unsigned b0, unsigned b1) {
    asm volatile(
        "mma.sync.aligned.m16n8k8.row.col.f32.tf32.tf32.f32 "
        "{%0,%1,%2,%3}, {%4,%5,%6,%7}, {%8,%9}, {%0,%1,%2,%3};\n"
        : "+f"(c[0]), "+f"(c[1]), "+f"(c[2]), "+f"(c[3])
        : "r"(a0), "r"(a1), "r"(a2), "r"(a3), "r"(b0), "r"(b1));
}

__device__ __forceinline__ float sigf(float x) {
    return __fdividef(1.f, 1.f + __expf(-x));
}
__device__ __forceinline__ float tanh_fast(float x) {
    return __fdividef(2.f, 1.f + __expf(-2.f * x)) - 1.f;
}

// ---------------- fc_in: enc = relu(backbone @ W^T + b) ----------------
// M=8192, N=128, K=4096.  CTA: 64x128, 256 thr (8 warps, warp 16x64). KC=16.
__global__ void __launch_bounds__(256) k_fcin(const float* __restrict__ A,
                                              const float* __restrict__ W,
                                              const float* __restrict__ bias,
                                              float* __restrict__ out) {
    __shared__ unsigned As[64][20];
    __shared__ unsigned Bs[128][20];
    const int tid  = threadIdx.x;
    const int lane = tid & 31;
    const int w    = tid >> 5;
    const int wm   = w & 3;     // 4 m-tiles of 16
    const int wn   = w >> 2;    // 2 n-tiles of 64
    const int row0 = blockIdx.x * 64;
    const int g    = lane >> 2;
    const int t4   = lane & 3;

    float acc[8][4];
#pragma unroll
    for (int i = 0; i < 8; i++)
#pragma unroll
        for (int j = 0; j < 4; j++) acc[i][j] = 0.f;

    for (int kc = 0; kc < ENCL / 16; kc++) {
        const int k0 = kc * 16;
        // A tile: 64 x 16 -> 256 float4, one per thread
        {
            int m = tid >> 2, kv = tid & 3;
            float4 v = *(const float4*)(A + (size_t)(row0 + m) * ENCL + k0 + kv * 4);
            *(uint4*)&As[m][kv * 4] = tf4(v);
        }
        // B tile: 128 x 16 -> 512 float4, two per thread
#pragma unroll
        for (int i = 0; i < 2; i++) {
            int idx = tid + i * 256;
            int n = idx >> 2, kv = idx & 3;
            float4 v = *(const float4*)(W + (size_t)n * ENCL + k0 + kv * 4);
            *(uint4*)&Bs[n][kv * 4] = tf4(v);
        }
        __syncthreads();
#pragma unroll
        for (int ks = 0; ks < 2; ks++) {
            const int kb = ks * 8;
            unsigned a0 = As[wm * 16 + g][kb + t4];
            unsigned a1 = As[wm * 16 + g + 8][kb + t4];
            unsigned a2 = As[wm * 16 + g][kb + t4 + 4];
            unsigned a3 = As[wm * 16 + g + 8][kb + t4 + 4];
#pragma unroll
            for (int nt = 0; nt < 8; nt++) {
                int col = wn * 64 + nt * 8 + g;
                unsigned b0 = Bs[col][kb + t4];
                unsigned b1 = Bs[col][kb + t4 + 4];
                mma_tf32(acc[nt], a0, a1, a2, a3, b0, b1);
            }
        }
        __syncthreads();
    }
    // epilogue: bias + relu
#pragma unroll
    for (int nt = 0; nt < 8; nt++)
#pragma unroll
        for (int cr = 0; cr < 4; cr++) {
            int r   = row0 + wm * 16 + g + (cr >> 1) * 8;
            int col = wn * 64 + nt * 8 + t4 * 2 + (cr & 1);
            float v = acc[nt][cr] + bias[col];
            out[r * HID + col] = fmaxf(v, 0.f);
        }
}

// ---------------- fused LSTM step ----------------
// gates = x_t @ Wih^T + h_{t-1} @ Whh^T + bih + bhh ; then cell.
// M=8192 (tile 64 -> 128 CTAs), N=512, K=256 (or 128 when t==0). 512 thr = 16 warps.
// Warp (wm,wn): rows wm*16..+15; columns {gate*128 + wn*32 + s8*8} for gate 0..3, s8 0..3
// -> each thread owns all 4 gates of its (b,j) cells: no smem exchange for the cell.
__global__ void __launch_bounds__(512) k_step(const float* __restrict__ Xt,
                                              const float* __restrict__ Hprev,
                                              const float* __restrict__ Wih,
                                              const float* __restrict__ Whh,
                                              const float* __restrict__ bih,
                                              const float* __restrict__ bhh,
                                              float* __restrict__ Cst,
                                              float* __restrict__ Hout,
                                              int t0) {
    __shared__ unsigned Bs[512][20];
    __shared__ unsigned As[64][20];
    const int tid  = threadIdx.x;
    const int lane = tid & 31;
    const int w    = tid >> 5;
    const int wm   = w & 3;     // 4 row tiles of 16
    const int wn   = w >> 2;    // 4 j-strips of 32
    const int row0 = blockIdx.x * 64;
    const int g    = lane >> 2;
    const int t4   = lane & 3;

    float acc[4][4][4];
#pragma unroll
    for (int a = 0; a < 4; a++)
#pragma unroll
        for (int b = 0; b < 4; b++)
#pragma unroll
            for (int c = 0; c < 4; c++) acc[a][b][c] = 0.f;

    const int nch = t0 ? 8 : 16;
    for (int kc = 0; kc < nch; kc++) {
        const float* Bsrc;
        const float* Asrc;
        int k0;
        if (kc < 8) { Bsrc = Wih; Asrc = Xt;    k0 = kc * 16; }
        else        { Bsrc = Whh; Asrc = Hprev; k0 = kc * 16 - 128; }

        // A tile: 64 x 16 -> 256 float4, threads 0..255
        if (tid < 256) {
            int m = tid >> 2, kv = tid & 3;
            float4 v = *(const float4*)(Asrc + (size_t)(row0 + m) * HID + k0 + kv * 4);
            *(uint4*)&As[m][kv * 4] = tf4(v);
        }
        // B tile: 512 x 16 -> 2048 float4, four per thread
#pragma unroll
        for (int i = 0; i < 4; i++) {
            int idx = tid + i * 512;
            int n = idx >> 2, kv = idx & 3;
            float4 v = *(const float4*)(Bsrc + (size_t)n * HID + k0 + kv * 4);
            *(uint4*)&Bs[n][kv * 4] = tf4(v);
        }
        __syncthreads();
#pragma unroll
        for (int ks = 0; ks < 2; ks++) {
            const int kb = ks * 8;
            unsigned a0 = As[wm * 16 + g][kb + t4];
            unsigned a1 = As[wm * 16 + g + 8][kb + t4];
            unsigned a2 = As[wm * 16 + g][kb + t4 + 4];
            unsigned a3 = As[wm * 16 + g + 8][kb + t4 + 4];
#pragma unroll
            for (int gt = 0; gt < 4; gt++)
#pragma unroll
                for (int s8 = 0; s8 < 4; s8++) {
                    int col = gt * 128 + wn * 32 + s8 * 8 + g;
                    unsigned b0 = Bs[col][kb + t4];
                    unsigned b1 = Bs[col][kb + t4 + 4];
                    mma_tf32(acc[gt][s8], a0, a1, a2, a3, b0, b1);
                }
        }
        __syncthreads();
    }

    // LSTM cell (all 4 gates in-register per thread)
#pragma unroll
    for (int s8 = 0; s8 < 4; s8++)
#pragma unroll
        for (int crH = 0; crH < 2; crH++)
#pragma unroll
            for (int crL = 0; crL < 2; crL++) {
                int cr = crH * 2 + crL;
                int b  = row0 + wm * 16 + g + crH * 8;
                int j  = wn * 32 + s8 * 8 + t4 * 2 + crL;
                float gi = acc[0][s8][cr] + bih[j]       + bhh[j];
                float gf = acc[1][s8][cr] + bih[128 + j] + bhh[128 + j];
                float gg = acc[2][s8][cr] + bih[256 + j] + bhh[256 + j];
                float go = acc[3][s8][cr] + bih[384 + j] + bhh[384 + j];
                float cold = t0 ? 0.f : Cst[b * HID + j];
                float cn   = sigf(gf) * cold + sigf(gi) * tanh_fast(gg);
                float h    = sigf(go) * tanh_fast(cn);
                Cst [b * HID + j] = cn;
                Hout[b * HID + j] = h;
            }
}

// ---------------- fc_out: fc = Y @ W^T + b, fused scatter ----------------
// Y: [T*B, 128] (rows = t*B + b). N = 75 (padded to 80). CTA: 128 rows, 256 thr.
__global__ void __launch_bounds__(256) k_fcout(const float* __restrict__ Y,
                                               const float* __restrict__ W,
                                               const float* __restrict__ bias,
                                               float* __restrict__ pred,
                                               float* __restrict__ plog) {
    __shared__ unsigned As[128][20];
    __shared__ unsigned Bs[80][20];
    const int tid  = threadIdx.x;
    const int lane = tid & 31;
    const int wm   = tid >> 5;   // 8 warps x 16 rows
    const int row0 = blockIdx.x * 128;
    const int g    = lane >> 2;
    const int t4   = lane & 3;

    float acc[10][4];
#pragma unroll
    for (int i = 0; i < 10; i++)
#pragma unroll
        for (int j = 0; j < 4; j++) acc[i][j] = 0.f;

    for (int kc = 0; kc < 8; kc++) {
        const int k0 = kc * 16;
        // A: 128 x 16 -> 512 float4, two per thread
#pragma unroll
        for (int i = 0; i < 2; i++) {
            int idx = tid + i * 256;
            int m = idx >> 2, kv = idx & 3;
            float4 v = *(const float4*)(Y + (size_t)(row0 + m) * HID + k0 + kv * 4);
            *(uint4*)&As[m][kv * 4] = tf4(v);
        }
        // B: 80 x 16 -> 320 float4 (rows >= 75 zero-padded)
#pragma unroll
        for (int i = 0; i < 2; i++) {
            int idx = tid + i * 256;
            if (idx < 320) {
                int n = idx >> 2, kv = idx & 3;
                float4 v = make_float4(0.f, 0.f, 0.f, 0.f);
                if (n < 75) v = *(const float4*)(W + (size_t)n * HID + k0 + kv * 4);
                *(uint4*)&Bs[n][kv * 4] = tf4(v);
            }
        }
        __syncthreads();
#pragma unroll
        for (int ks = 0; ks < 2; ks++) {
            const int kb = ks * 8;
            unsigned a0 = As[wm * 16 + g][kb + t4];
            unsigned a1 = As[wm * 16 + g + 8][kb + t4];
            unsigned a2 = As[wm * 16 + g][kb + t4 + 4];
            unsigned a3 = As[wm * 16 + g + 8][kb + t4 + 4];
#pragma unroll
            for (int nt = 0; nt < 10; nt++) {
                int col = nt * 8 + g;
                unsigned b0 = Bs[col][kb + t4];
                unsigned b1 = Bs[col][kb + t4 + 4];
                mma_tf32(acc[nt], a0, a1, a2, a3, b0, b1);
            }
        }
        __syncthreads();
    }
    // scatter epilogue
#pragma unroll
    for (int nt = 0; nt < 10; nt++)
#pragma unroll
        for (int cr = 0; cr < 4; cr++) {
            int col = nt * 8 + t4 * 2 + (cr & 1);
            if (col >= 75) continue;
            int r = row0 + wm * 16 + g + (cr >> 1) * 8;
            int t = r >> 13;         // / BATCH (8192)
            int b = r & (BATCH - 1);
            float v = acc[nt][cr] + bias[col];
            if (col < 50) {
                int m = col >> 1, d = col & 1;
                pred[b * (NMODES * TT * 2) + m * (TT * 2) + t * 2 + d] = v;
            } else if (t == TT - 1) {
                plog[b * NMODES + (col - 50)] = v;
            }
        }
}

// ---------------- softmax over 25 modes ----------------
__global__ void __launch_bounds__(256) k_softmax(const float* __restrict__ plog,
                                                 float* __restrict__ out) {
    int b = blockIdx.x * blockDim.x + threadIdx.x;
    if (b >= BATCH) return;
    float v[NMODES];
    float m = -1e30f;
#pragma unroll
    for (int j = 0; j < NMODES; j++) {
        v[j] = plog[b * NMODES + j];
        m = fmaxf(m, v[j]);
    }
    float s = 0.f;
#pragma unroll
    for (int j = 0; j < NMODES; j++) {
        v[j] = __expf(v[j] - m);
        s += v[j];
    }
    float inv = __fdividef(1.f, s);
#pragma unroll
    for (int j = 0; j < NMODES; j++) out[b * NMODES + j] = v[j] * inv;
}

// ---------------- launcher ----------------
extern "C" void kernel_launch(void* const* d_in, const int* in_sizes, int n_in,
                              void* d_out, int out_size) {
    const float* backbone = (const float*)d_in[0];
    const float* fcW      = (const float*)d_in[1];
    const float* fcb      = (const float*)d_in[2];
    const float* Wih      = (const float*)d_in[3];
    const float* Whh      = (const float*)d_in[4];
    const float* bih      = (const float*)d_in[5];
    const float* bhh      = (const float*)d_in[6];
    const float* foW      = (const float*)d_in[7];
    const float* fob      = (const float*)d_in[8];

    float* out  = (float*)d_out;
    float* pred = out;
    float* prob = out + (size_t)BATCH * NMODES * TT * 2;

    float *encb, *pXa, *pXb, *cbuf, *plogb;
    cudaGetSymbolAddress((void**)&encb,  g_enc);
    cudaGetSymbolAddress((void**)&pXa,   g_Xa);
    cudaGetSymbolAddress((void**)&pXb,   g_Xb);
    cudaGetSymbolAddress((void**)&cbuf,  g_c);
    cudaGetSymbolAddress((void**)&plogb, g_plog);

    k_fcin<<<BATCH / 64, 256>>>(backbone, fcW, fcb, encb);

    const float* Xin = encb;
    bool  layer0 = true;
    float* Xout = pXa;
    for (int l = 0; l < LAYERS; l++) {
        const float* Wl  = Wih + (size_t)l * G4 * HID;
        const float* Ul  = Whh + (size_t)l * G4 * HID;
        const float* bl  = bih + (size_t)l * G4;
        const float* b2l = bhh + (size_t)l * G4;
        for (int t = 0; t < TT; t++) {
            const float* xt = layer0 ? encb : (Xin + (size_t)t * BATCH * HID);
            const float* hp = (t == 0) ? encb /*unused*/ : (Xout + (size_t)(t - 1) * BATCH * HID);
            k_step<<<BATCH / 64, 512>>>(xt, hp, Wl, Ul, bl, b2l, cbuf,
                                        Xout + (size_t)t * BATCH * HID, t == 0 ? 1 : 0);
        }
        Xin   = Xout;
        layer0 = false;
        Xout  = (Xout == pXa) ? pXb : pXa;
    }

    k_fcout<<<(TT * BATCH) / 128, 256>>>(Xin, foW, fob, pred, plogb);
    k_softmax<<<BATCH / 256, 256>>>(plogb, prob);
}

// round 9
// speedup vs baseline: 1.5319x; 1.5251x over previous
#include <cuda_runtime.h>
#include <cuda_bf16.h>

#define BATCH   8192
#define HID     128
#define TT      12
#define LAYERS  10
#define G4      512
#define ENCL    4096
#define NMODES  25

// ---------------- scratch (static device globals; no allocation) ----------------
__device__ unsigned g_encp[BATCH * HID];                 // enc as tf32 words
__device__ unsigned g_Xa  [TT * BATCH * HID];            // inter-layer x (tf32 words)
__device__ unsigned g_Xb  [TT * BATCH * HID];
__device__ unsigned g_Wp  [LAYERS * 16 * 512 * 16];      // packed tf32 weights [l][kc][n][16]
__device__ float    g_plog[BATCH * NMODES];

// ---------------- helpers ----------------
__device__ __forceinline__ unsigned f2tf(float x) {
    unsigned u;
    asm("cvt.rna.tf32.f32 %0, %1;" : "=r"(u) : "f"(x));
    return u;
}
__device__ __forceinline__ uint4 tf4(float4 v) {
    uint4 u; u.x = f2tf(v.x); u.y = f2tf(v.y); u.z = f2tf(v.z); u.w = f2tf(v.w);
    return u;
}
__device__ __forceinline__ void mma_tf32(float c[4],
                                         unsigned a0, unsigned a1, unsigned a2, unsigned a3,
                                         unsigned b0, unsigned b1) {
    asm volatile(
        "mma.sync.aligned.m16n8k8.row.col.f32.tf32.tf32.f32 "
        "{%0,%1,%2,%3}, {%4,%5,%6,%7}, {%8,%9}, {%0,%1,%2,%3};\n"
        : "+f"(c[0]), "+f"(c[1]), "+f"(c[2]), "+f"(c[3])
        : "r"(a0), "r"(a1), "r"(a2), "r"(a3), "r"(b0), "r"(b1));
}
__device__ __forceinline__ float sigf(float x) { return __fdividef(1.f, 1.f + __expf(-x)); }
__device__ __forceinline__ float tanh_fast(float x) { return __fdividef(2.f, 1.f + __expf(-2.f * x)) - 1.f; }

__device__ __forceinline__ void cp16(unsigned* dst_smem, const unsigned* src) {
    unsigned d = (unsigned)__cvta_generic_to_shared(dst_smem);
    asm volatile("cp.async.cg.shared.global [%0], [%1], 16;\n" :: "r"(d), "l"(src));
}
#define CP_COMMIT() asm volatile("cp.async.commit_group;\n" ::: "memory")
#define CP_WAIT1()  asm volatile("cp.async.wait_group 1;\n" ::: "memory")
#define CP_WAIT0()  asm volatile("cp.async.wait_group 0;\n" ::: "memory")

// ---------------- weight pre-pack: tf32, chunked [l][kc][n][16] ----------------
__global__ void __launch_bounds__(256) k_pack(const float* __restrict__ Wih,
                                              const float* __restrict__ Whh,
                                              unsigned* __restrict__ Wp) {
    int idx = blockIdx.x * 256 + threadIdx.x;
    if (idx >= LAYERS * 16 * 512 * 16) return;
    int w  = idx & 15;
    int n  = (idx >> 4) & 511;
    int kc = (idx >> 13) & 15;
    int l  = idx >> 17;
    float v;
    if (kc < 8) v = Wih[((size_t)l * 512 + n) * 128 + kc * 16 + w];
    else        v = Whh[((size_t)l * 512 + n) * 128 + (kc - 8) * 16 + w];
    Wp[idx] = f2tf(v);
}

// ---------------- fc_in: enc = tf32(relu(backbone @ W^T + b)) ----------------
__global__ void __launch_bounds__(256) k_fcin(const float* __restrict__ A,
                                              const float* __restrict__ W,
                                              const float* __restrict__ bias,
                                              unsigned* __restrict__ out) {
    __shared__ unsigned As[64][20];
    __shared__ unsigned Bs[128][20];
    const int tid  = threadIdx.x;
    const int lane = tid & 31;
    const int w    = tid >> 5;
    const int wm   = w & 3;
    const int wn   = w >> 2;
    const int row0 = blockIdx.x * 64;
    const int g    = lane >> 2;
    const int t4   = lane & 3;

    float acc[8][4];
#pragma unroll
    for (int i = 0; i < 8; i++)
#pragma unroll
        for (int j = 0; j < 4; j++) acc[i][j] = 0.f;

    for (int kc = 0; kc < ENCL / 16; kc++) {
        const int k0 = kc * 16;
        {
            int m = tid >> 2, kv = tid & 3;
            float4 v = *(const float4*)(A + (size_t)(row0 + m) * ENCL + k0 + kv * 4);
            *(uint4*)&As[m][kv * 4] = tf4(v);
        }
#pragma unroll
        for (int i = 0; i < 2; i++) {
            int idx = tid + i * 256;
            int n = idx >> 2, kv = idx & 3;
            float4 v = *(const float4*)(W + (size_t)n * ENCL + k0 + kv * 4);
            *(uint4*)&Bs[n][kv * 4] = tf4(v);
        }
        __syncthreads();
#pragma unroll
        for (int ks = 0; ks < 2; ks++) {
            const int kb = ks * 8;
            unsigned a0 = As[wm * 16 + g][kb + t4];
            unsigned a1 = As[wm * 16 + g + 8][kb + t4];
            unsigned a2 = As[wm * 16 + g][kb + t4 + 4];
            unsigned a3 = As[wm * 16 + g + 8][kb + t4 + 4];
#pragma unroll
            for (int nt = 0; nt < 8; nt++) {
                int col = wn * 64 + nt * 8 + g;
                unsigned b0 = Bs[col][kb + t4];
                unsigned b1 = Bs[col][kb + t4 + 4];
                mma_tf32(acc[nt], a0, a1, a2, a3, b0, b1);
            }
        }
        __syncthreads();
    }
#pragma unroll
    for (int nt = 0; nt < 8; nt++)
#pragma unroll
        for (int cr = 0; cr < 4; cr++) {
            int r   = row0 + wm * 16 + g + (cr >> 1) * 8;
            int col = wn * 64 + nt * 8 + t4 * 2 + (cr & 1);
            float v = acc[nt][cr] + bias[col];
            out[r * HID + col] = f2tf(fmaxf(v, 0.f));
        }
}

// ---------------- persistent fused LSTM: all layers, all timesteps ----------------
// grid 128 CTAs (64 batch rows each), 512 threads = 16 warps (wm in {0,1}: 32 rows;
// wn in 0..7: 16 j-cols x 4 gates). Dynamic smem layout (words):
#define SM_XS   (2 * 512 * 20)            // Bs: [2][512][20]
#define SM_HS   (SM_XS + 8 * 64 * 20)     // Xs: [8][64][20]
#define SM_CS   (SM_HS + 8 * 64 * 20)     // Hs: [8][64][20]
#define SM_BIAS (SM_CS + 16 * 512)        // Cs: [16][512] floats
#define SM_WORDS (SM_BIAS + 512)          // bias: 512 floats
#define SMEM_BYTES (SM_WORDS * 4)         // 198656

__global__ void __launch_bounds__(512, 1) k_lstm(const unsigned* __restrict__ enc,
                                                 const unsigned* __restrict__ Wp,
                                                 const float* __restrict__ bih,
                                                 const float* __restrict__ bhh,
                                                 unsigned* __restrict__ Xa,
                                                 unsigned* __restrict__ Xb) {
    extern __shared__ unsigned sm[];
    unsigned* Bs = sm;
    unsigned* Xs = sm + SM_XS;
    unsigned* Hs = sm + SM_HS;
    float*    Cs = (float*)(sm + SM_CS);
    float*    bs = (float*)(sm + SM_BIAS);

    const int tid  = threadIdx.x;
    const int lane = tid & 31;
    const int w    = tid >> 5;
    const int wm   = w & 1;
    const int wn   = w >> 1;
    const int g    = lane >> 2;
    const int t4   = lane & 3;
    const int row0 = blockIdx.x * 64;

    // ---- init (layer 0) ----
    bs[tid] = bih[tid] + bhh[tid];
#pragma unroll
    for (int i = 0; i < 16; i++) Cs[i * 512 + tid] = 0.f;
    for (int i = tid; i < 8 * 64 * 20; i += 512) Hs[i] = 0;
    for (int i = tid; i < 8192; i += 512) {   // Xs <- enc (t-invariant for layer 0)
        int ww = i & 15, r = (i >> 4) & 63, c = i >> 10;
        Xs[c * 1280 + r * 20 + ww] = enc[(size_t)(row0 + r) * 128 + c * 16 + ww];
    }
    __syncthreads();

    auto issueB = [&](int l, int kc, int buf) {
        const unsigned* src = Wp + (((size_t)l * 16 + kc) << 13);
        unsigned* dst = Bs + buf * 10240;
#pragma unroll
        for (int i = 0; i < 4; i++) {
            int idx = i * 512 + tid;              // [0,2048)
            int n = idx >> 2, seg = idx & 3;
            cp16(dst + n * 20 + seg * 4, src + idx * 4);
        }
    };
    auto issueX = [&](const unsigned* src_t) {    // one timestep block [B][128]
#pragma unroll
        for (int i = 0; i < 4; i++) {
            int idx = i * 512 + tid;              // [0,2048)
            int c = idx >> 8, r = (idx >> 2) & 63, seg = idx & 3;
            cp16(Xs + c * 1280 + r * 20 + seg * 4,
                 src_t + (size_t)(row0 + r) * 128 + c * 16 + seg * 4);
        }
    };

    // pipeline prologue: chunks 0 and 1 of layer 0
    issueB(0, 0, 0); CP_COMMIT();
    issueB(0, 1, 1); CP_COMMIT();

    const unsigned* Xin = Xa;     // unused while l==0
    unsigned*       Xout = Xa;

    float acc[2][8][4];
    int gctr = 0;                 // flattened chunk counter: l*192 + t*16 + kc

    for (int l = 0; l < LAYERS; l++) {
        for (int t = 0; t < TT; t++) {
#pragma unroll
            for (int a = 0; a < 2; a++)
#pragma unroll
                for (int b = 0; b < 8; b++)
#pragma unroll
                    for (int q = 0; q < 4; q++) acc[a][b][q] = 0.f;

            for (int kc = 0; kc < 16; kc++) {
                CP_WAIT1();
                __syncthreads();
                const unsigned* Bb   = Bs + (gctr & 1) * 10240;
                const unsigned* Asrc = (kc < 8) ? (Xs + kc * 1280) : (Hs + (kc - 8) * 1280);
#pragma unroll
                for (int ks = 0; ks < 2; ks++) {
                    const int kb = ks * 8;
                    unsigned a0[2], a1[2], a2[2], a3[2];
#pragma unroll
                    for (int m = 0; m < 2; m++) {
                        int mr = wm * 32 + m * 16;
                        a0[m] = Asrc[(mr + g) * 20 + kb + t4];
                        a1[m] = Asrc[(mr + g + 8) * 20 + kb + t4];
                        a2[m] = Asrc[(mr + g) * 20 + kb + t4 + 4];
                        a3[m] = Asrc[(mr + g + 8) * 20 + kb + t4 + 4];
                    }
#pragma unroll
                    for (int nf = 0; nf < 8; nf++) {
                        int col = (nf >> 1) * 128 + wn * 16 + (nf & 1) * 8 + g;
                        unsigned b0 = Bb[col * 20 + kb + t4];
                        unsigned b1 = Bb[col * 20 + kb + t4 + 4];
                        mma_tf32(acc[0][nf], a0[0], a1[0], a2[0], a3[0], b0, b1);
                        mma_tf32(acc[1][nf], a0[1], a1[1], a2[1], a3[1], b0, b1);
                    }
                }
                __syncthreads();
                // prefetch chunk gctr+2 (weights cycle every t, continue across l)
                int gn = gctr + 2;
                if (gn < LAYERS * 192) {
                    int ln = gn / 192;
                    issueB(ln, (gn % 192) & 15, gn & 1);
                }
                if (kc == 7) {   // x prefetch rides in this group
                    if (t < TT - 1) {
                        if (l > 0) issueX(Xin + (size_t)(t + 1) * BATCH * 128);
                    } else if (l < LAYERS - 1) {
                        issueX(Xout);   // (l+1, t=0): this layer's t=0 output (already written)
                    }
                }
                CP_COMMIT();
                gctr++;
            }

            // ---- cell epilogue: all 4 gates in-register ----
#pragma unroll
            for (int m = 0; m < 2; m++)
#pragma unroll
                for (int s2 = 0; s2 < 2; s2++)
#pragma unroll
                    for (int q = 0; q < 2; q++)
#pragma unroll
                        for (int d = 0; d < 2; d++) {
                            int r  = wm * 32 + m * 16 + q * 8 + g;
                            int j  = wn * 16 + s2 * 8 + t4 * 2 + d;
                            int cr = q * 2 + d;
                            float gi = acc[m][0 + s2][cr] + bs[j];
                            float gf = acc[m][2 + s2][cr] + bs[128 + j];
                            float gg = acc[m][4 + s2][cr] + bs[256 + j];
                            float go = acc[m][6 + s2][cr] + bs[384 + j];
                            int ci = m * 8 + s2 * 4 + q * 2 + d;
                            float cold = Cs[ci * 512 + tid];
                            float cn = sigf(gf) * cold + sigf(gi) * tanh_fast(gg);
                            float h  = sigf(go) * tanh_fast(cn);
                            Cs[ci * 512 + tid] = cn;
                            unsigned hw = f2tf(h);
                            Hs[wn * 1280 + r * 20 + (j & 15)] = hw;
                            Xout[((size_t)t * BATCH + row0 + r) * 128 + j] = hw;
                        }
            // next t's chunk-0 barrier orders these writes before any reader
        }
        // ---- layer transition ----
        __syncthreads();   // all epilogue reads of bs/Hs done before rewrite
        if (l + 1 < LAYERS) {
            bs[tid] = bih[(l + 1) * 512 + tid] + bhh[(l + 1) * 512 + tid];
#pragma unroll
            for (int i = 0; i < 16; i++) Cs[i * 512 + tid] = 0.f;
            for (int i = tid; i < 8 * 64 * 20; i += 512) Hs[i] = 0;
            Xin  = Xout;
            Xout = (Xout == Xa) ? Xb : Xa;
        }
    }
    CP_WAIT0();
}

// ---------------- fc_out: fc = Y @ W^T + b, fused scatter (Y is tf32 words) ----------------
__global__ void __launch_bounds__(256) k_fcout(const unsigned* __restrict__ Y,
                                               const float* __restrict__ W,
                                               const float* __restrict__ bias,
                                               float* __restrict__ pred,
                                               float* __restrict__ plog) {
    __shared__ unsigned As[128][20];
    __shared__ unsigned Bs[80][20];
    const int tid  = threadIdx.x;
    const int lane = tid & 31;
    const int wm   = tid >> 5;
    const int row0 = blockIdx.x * 128;
    const int g    = lane >> 2;
    const int t4   = lane & 3;

    float acc[10][4];
#pragma unroll
    for (int i = 0; i < 10; i++)
#pragma unroll
        for (int j = 0; j < 4; j++) acc[i][j] = 0.f;

    for (int kc = 0; kc < 8; kc++) {
        const int k0 = kc * 16;
#pragma unroll
        for (int i = 0; i < 2; i++) {
            int idx = tid + i * 256;
            int m = idx >> 2, kv = idx & 3;
            uint4 v = *(const uint4*)(Y + (size_t)(row0 + m) * HID + k0 + kv * 4);
            *(uint4*)&As[m][kv * 4] = v;
        }
#pragma unroll
        for (int i = 0; i < 2; i++) {
            int idx = tid + i * 256;
            if (idx < 320) {
                int n = idx >> 2, kv = idx & 3;
                float4 v = make_float4(0.f, 0.f, 0.f, 0.f);
                if (n < 75) v = *(const float4*)(W + (size_t)n * HID + k0 + kv * 4);
                *(uint4*)&Bs[n][kv * 4] = tf4(v);
            }
        }
        __syncthreads();
#pragma unroll
        for (int ks = 0; ks < 2; ks++) {
            const int kb = ks * 8;
            unsigned a0 = As[wm * 16 + g][kb + t4];
            unsigned a1 = As[wm * 16 + g + 8][kb + t4];
            unsigned a2 = As[wm * 16 + g][kb + t4 + 4];
            unsigned a3 = As[wm * 16 + g + 8][kb + t4 + 4];
#pragma unroll
            for (int nt = 0; nt < 10; nt++) {
                int col = nt * 8 + g;
                unsigned b0 = Bs[col][kb + t4];
                unsigned b1 = Bs[col][kb + t4 + 4];
                mma_tf32(acc[nt], a0, a1, a2, a3, b0, b1);
            }
        }
        __syncthreads();
    }
#pragma unroll
    for (int nt = 0; nt < 10; nt++)
#pragma unroll
        for (int cr = 0; cr < 4; cr++) {
            int col = nt * 8 + t4 * 2 + (cr & 1);
            if (col >= 75) continue;
            int r = row0 + wm * 16 + g + (cr >> 1) * 8;
            int t = r >> 13;
            int b = r & (BATCH - 1);
            float v = acc[nt][cr] + bias[col];
            if (col < 50) {
                int m = col >> 1, d = col & 1;
                pred[b * (NMODES * TT * 2) + m * (TT * 2) + t * 2 + d] = v;
            } else if (t == TT - 1) {
                plog[b * NMODES + (col - 50)] = v;
            }
        }
}

// ---------------- softmax over 25 modes ----------------
__global__ void __launch_bounds__(256) k_softmax(const float* __restrict__ plog,
                                                 float* __restrict__ out) {
    int b = blockIdx.x * blockDim.x + threadIdx.x;
    if (b >= BATCH) return;
    float v[NMODES];
    float m = -1e30f;
#pragma unroll
    for (int j = 0; j < NMODES; j++) {
        v[j] = plog[b * NMODES + j];
        m = fmaxf(m, v[j]);
    }
    float s = 0.f;
#pragma unroll
    for (int j = 0; j < NMODES; j++) {
        v[j] = __expf(v[j] - m);
        s += v[j];
    }
    float inv = __fdividef(1.f, s);
#pragma unroll
    for (int j = 0; j < NMODES; j++) out[b * NMODES + j] = v[j] * inv;
}

// ---------------- launcher ----------------
extern "C" void kernel_launch(void* const* d_in, const int* in_sizes, int n_in,
                              void* d_out, int out_size) {
    const float* backbone = (const float*)d_in[0];
    const float* fcW      = (const float*)d_in[1];
    const float* fcb      = (const float*)d_in[2];
    const float* Wih      = (const float*)d_in[3];
    const float* Whh      = (const float*)d_in[4];
    const float* bih      = (const float*)d_in[5];
    const float* bhh      = (const float*)d_in[6];
    const float* foW      = (const float*)d_in[7];
    const float* fob      = (const float*)d_in[8];

    float* out  = (float*)d_out;
    float* pred = out;
    float* prob = out + (size_t)BATCH * NMODES * TT * 2;

    unsigned *encp, *pXa, *pXb, *wp;
    float* plogb;
    cudaGetSymbolAddress((void**)&encp,  g_encp);
    cudaGetSymbolAddress((void**)&pXa,   g_Xa);
    cudaGetSymbolAddress((void**)&pXb,   g_Xb);
    cudaGetSymbolAddress((void**)&wp,    g_Wp);
    cudaGetSymbolAddress((void**)&plogb, g_plog);

    cudaFuncSetAttribute(k_lstm, cudaFuncAttributeMaxDynamicSharedMemorySize, SMEM_BYTES);

    k_pack<<<(LAYERS * 16 * 512 * 16 + 255) / 256, 256>>>(Wih, Whh, wp);
    k_fcin<<<BATCH / 64, 256>>>(backbone, fcW, fcb, encp);
    k_lstm<<<BATCH / 64, 512, SMEM_BYTES>>>(encp, wp, bih, bhh, pXa, pXb);
    // LAYERS = 10 (even): final output lives in g_Xb
    k_fcout<<<(TT * BATCH) / 128, 256>>>(pXb, foW, fob, pred, plogb);
    k_softmax<<<BATCH / 256, 256>>>(plogb, prob);
}

// round 10
// speedup vs baseline: 1.5333x; 1.0009x over previous
#include <cuda_runtime.h>
#include <cuda_bf16.h>

#define BATCH   8192
#define HID     128
#define TT      12
#define LAYERS  10
#define G4      512
#define ENCL    4096
#define NMODES  25

// ---------------- scratch (static device globals; no allocation) ----------------
__device__ unsigned g_encp[BATCH * HID];                 // enc as tf32 words
__device__ unsigned g_Xa  [TT * BATCH * HID];            // inter-layer x (tf32 words)
__device__ unsigned g_Xb  [TT * BATCH * HID];
__device__ unsigned g_Wp  [LAYERS * 16 * 512 * 16];      // packed tf32 weights [l][kc][n][16]
__device__ float    g_plog[BATCH * NMODES];

// ---------------- helpers ----------------
__device__ __forceinline__ unsigned f2tf(float x) {
    unsigned u;
    asm("cvt.rna.tf32.f32 %0, %1;" : "=r"(u) : "f"(x));
    return u;
}
__device__ __forceinline__ uint4 tf4(float4 v) {
    uint4 u; u.x = f2tf(v.x); u.y = f2tf(v.y); u.z = f2tf(v.z); u.w = f2tf(v.w);
    return u;
}
__device__ __forceinline__ void mma_tf32(float c[4],
                                         unsigned a0, unsigned a1, unsigned a2, unsigned a3,
                                         unsigned b0, unsigned b1) {
    asm volatile(
        "mma.sync.aligned.m16n8k8.row.col.f32.tf32.tf32.f32 "
        "{%0,%1,%2,%3}, {%4,%5,%6,%7}, {%8,%9}, {%0,%1,%2,%3};\n"
        : "+f"(c[0]), "+f"(c[1]), "+f"(c[2]), "+f"(c[3])
        : "r"(a0), "r"(a1), "r"(a2), "r"(a3), "r"(b0), "r"(b1));
}
__device__ __forceinline__ float sigf(float x) { return __fdividef(1.f, 1.f + __expf(-x)); }
__device__ __forceinline__ float tanh_fast(float x) { return __fdividef(2.f, 1.f + __expf(-2.f * x)) - 1.f; }

__device__ __forceinline__ void cp16(unsigned* dst_smem, const unsigned* src) {
    unsigned d = (unsigned)__cvta_generic_to_shared(dst_smem);
    asm volatile("cp.async.cg.shared.global [%0], [%1], 16;\n" :: "r"(d), "l"(src));
}
#define CP_COMMIT() asm volatile("cp.async.commit_group;\n" ::: "memory")
#define CP_WAIT1()  asm volatile("cp.async.wait_group 1;\n" ::: "memory")
#define CP_WAIT0()  asm volatile("cp.async.wait_group 0;\n" ::: "memory")

// ---------------- weight pre-pack: tf32, chunked [l][kc][n][16] ----------------
__global__ void __launch_bounds__(256) k_pack(const float* __restrict__ Wih,
                                              const float* __restrict__ Whh,
                                              unsigned* __restrict__ Wp) {
    int idx = blockIdx.x * 256 + threadIdx.x;
    if (idx >= LAYERS * 16 * 512 * 16) return;
    int w  = idx & 15;
    int n  = (idx >> 4) & 511;
    int kc = (idx >> 13) & 15;
    int l  = idx >> 17;
    float v;
    if (kc < 8) v = Wih[((size_t)l * 512 + n) * 128 + kc * 16 + w];
    else        v = Whh[((size_t)l * 512 + n) * 128 + (kc - 8) * 16 + w];
    Wp[idx] = f2tf(v);
}

// ---------------- fc_in: enc = tf32(relu(backbone @ W^T + b)) ----------------
__global__ void __launch_bounds__(256) k_fcin(const float* __restrict__ A,
                                              const float* __restrict__ W,
                                              const float* __restrict__ bias,
                                              unsigned* __restrict__ out) {
    __shared__ unsigned As[64][20];
    __shared__ unsigned Bs[128][20];
    const int tid  = threadIdx.x;
    const int lane = tid & 31;
    const int w    = tid >> 5;
    const int wm   = w & 3;
    const int wn   = w >> 2;
    const int row0 = blockIdx.x * 64;
    const int g    = lane >> 2;
    const int t4   = lane & 3;

    float acc[8][4];
#pragma unroll
    for (int i = 0; i < 8; i++)
#pragma unroll
        for (int j = 0; j < 4; j++) acc[i][j] = 0.f;

    for (int kc = 0; kc < ENCL / 16; kc++) {
        const int k0 = kc * 16;
        {
            int m = tid >> 2, kv = tid & 3;
            float4 v = *(const float4*)(A + (size_t)(row0 + m) * ENCL + k0 + kv * 4);
            *(uint4*)&As[m][kv * 4] = tf4(v);
        }
#pragma unroll
        for (int i = 0; i < 2; i++) {
            int idx = tid + i * 256;
            int n = idx >> 2, kv = idx & 3;
            float4 v = *(const float4*)(W + (size_t)n * ENCL + k0 + kv * 4);
            *(uint4*)&Bs[n][kv * 4] = tf4(v);
        }
        __syncthreads();
#pragma unroll
        for (int ks = 0; ks < 2; ks++) {
            const int kb = ks * 8;
            unsigned a0 = As[wm * 16 + g][kb + t4];
            unsigned a1 = As[wm * 16 + g + 8][kb + t4];
            unsigned a2 = As[wm * 16 + g][kb + t4 + 4];
            unsigned a3 = As[wm * 16 + g + 8][kb + t4 + 4];
#pragma unroll
            for (int nt = 0; nt < 8; nt++) {
                int col = wn * 64 + nt * 8 + g;
                unsigned b0 = Bs[col][kb + t4];
                unsigned b1 = Bs[col][kb + t4 + 4];
                mma_tf32(acc[nt], a0, a1, a2, a3, b0, b1);
            }
        }
        __syncthreads();
    }
#pragma unroll
    for (int nt = 0; nt < 8; nt++)
#pragma unroll
        for (int cr = 0; cr < 4; cr++) {
            int r   = row0 + wm * 16 + g + (cr >> 1) * 8;
            int col = wn * 64 + nt * 8 + t4 * 2 + (cr & 1);
            float v = acc[nt][cr] + bias[col];
            out[r * HID + col] = f2tf(fmaxf(v, 0.f));
        }
}

// ---------------- persistent fused LSTM: all layers, all timesteps ----------------
// grid 128 CTAs (64 batch rows each), 512 threads = 16 warps (wm in {0,1}: 32 rows;
// wn in 0..7: 16 j-cols x 4 gates). Dynamic smem layout (words):
#define SM_XS   (2 * 512 * 20)            // Bs: [2][512][20]
#define SM_HS   (SM_XS + 8 * 64 * 20)     // Xs: [8][64][20]
#define SM_CS   (SM_HS + 8 * 64 * 20)     // Hs: [8][64][20]
#define SM_BIAS (SM_CS + 16 * 512)        // Cs: [16][512] floats
#define SM_WORDS (SM_BIAS + 512)          // bias: 512 floats
#define SMEM_BYTES (SM_WORDS * 4)         // 198656

__global__ void __launch_bounds__(512, 1) k_lstm(const unsigned* __restrict__ enc,
                                                 const unsigned* __restrict__ Wp,
                                                 const float* __restrict__ bih,
                                                 const float* __restrict__ bhh,
                                                 unsigned* __restrict__ Xa,
                                                 unsigned* __restrict__ Xb) {
    extern __shared__ unsigned sm[];
    unsigned* Bs = sm;
    unsigned* Xs = sm + SM_XS;
    unsigned* Hs = sm + SM_HS;
    float*    Cs = (float*)(sm + SM_CS);
    float*    bs = (float*)(sm + SM_BIAS);

    const int tid  = threadIdx.x;
    const int lane = tid & 31;
    const int w    = tid >> 5;
    const int wm   = w & 1;
    const int wn   = w >> 1;
    const int g    = lane >> 2;
    const int t4   = lane & 3;
    const int row0 = blockIdx.x * 64;

    // ---- init (layer 0) ----
    bs[tid] = bih[tid] + bhh[tid];
#pragma unroll
    for (int i = 0; i < 16; i++) Cs[i * 512 + tid] = 0.f;
    for (int i = tid; i < 8 * 64 * 20; i += 512) Hs[i] = 0;
    for (int i = tid; i < 8192; i += 512) {   // Xs <- enc (t-invariant for layer 0)
        int ww = i & 15, r = (i >> 4) & 63, c = i >> 10;
        Xs[c * 1280 + r * 20 + ww] = enc[(size_t)(row0 + r) * 128 + c * 16 + ww];
    }
    __syncthreads();

    auto issueB = [&](int l, int kc, int buf) {
        const unsigned* src = Wp + (((size_t)l * 16 + kc) << 13);
        unsigned* dst = Bs + buf * 10240;
#pragma unroll
        for (int i = 0; i < 4; i++) {
            int idx = i * 512 + tid;              // [0,2048)
            int n = idx >> 2, seg = idx & 3;
            cp16(dst + n * 20 + seg * 4, src + idx * 4);
        }
    };
    auto issueX = [&](const unsigned* src_t) {    // one timestep block [B][128]
#pragma unroll
        for (int i = 0; i < 4; i++) {
            int idx = i * 512 + tid;              // [0,2048)
            int c = idx >> 8, r = (idx >> 2) & 63, seg = idx & 3;
            cp16(Xs + c * 1280 + r * 20 + seg * 4,
                 src_t + (size_t)(row0 + r) * 128 + c * 16 + seg * 4);
        }
    };

    // pipeline prologue: chunks 0 and 1 of layer 0
    issueB(0, 0, 0); CP_COMMIT();
    issueB(0, 1, 1); CP_COMMIT();

    const unsigned* Xin = Xa;     // unused while l==0
    unsigned*       Xout = Xa;

    float acc[2][8][4];
    int gctr = 0;                 // flattened chunk counter: l*192 + t*16 + kc

    for (int l = 0; l < LAYERS; l++) {
        for (int t = 0; t < TT; t++) {
#pragma unroll
            for (int a = 0; a < 2; a++)
#pragma unroll
                for (int b = 0; b < 8; b++)
#pragma unroll
                    for (int q = 0; q < 4; q++) acc[a][b][q] = 0.f;

            for (int kc = 0; kc < 16; kc++) {
                CP_WAIT1();
                __syncthreads();
                const unsigned* Bb   = Bs + (gctr & 1) * 10240;
                const unsigned* Asrc = (kc < 8) ? (Xs + kc * 1280) : (Hs + (kc - 8) * 1280);
#pragma unroll
                for (int ks = 0; ks < 2; ks++) {
                    const int kb = ks * 8;
                    unsigned a0[2], a1[2], a2[2], a3[2];
#pragma unroll
                    for (int m = 0; m < 2; m++) {
                        int mr = wm * 32 + m * 16;
                        a0[m] = Asrc[(mr + g) * 20 + kb + t4];
                        a1[m] = Asrc[(mr + g + 8) * 20 + kb + t4];
                        a2[m] = Asrc[(mr + g) * 20 + kb + t4 + 4];
                        a3[m] = Asrc[(mr + g + 8) * 20 + kb + t4 + 4];
                    }
#pragma unroll
                    for (int nf = 0; nf < 8; nf++) {
                        int col = (nf >> 1) * 128 + wn * 16 + (nf & 1) * 8 + g;
                        unsigned b0 = Bb[col * 20 + kb + t4];
                        unsigned b1 = Bb[col * 20 + kb + t4 + 4];
                        mma_tf32(acc[0][nf], a0[0], a1[0], a2[0], a3[0], b0, b1);
                        mma_tf32(acc[1][nf], a0[1], a1[1], a2[1], a3[1], b0, b1);
                    }
                }
                __syncthreads();
                // prefetch chunk gctr+2 (weights cycle every t, continue across l)
                int gn = gctr + 2;
                if (gn < LAYERS * 192) {
                    int ln = gn / 192;
                    issueB(ln, (gn % 192) & 15, gn & 1);
                }
                if (kc == 7) {   // x prefetch rides in this group
                    if (t < TT - 1) {
                        if (l > 0) issueX(Xin + (size_t)(t + 1) * BATCH * 128);
                    } else if (l < LAYERS - 1) {
                        issueX(Xout);   // (l+1, t=0): this layer's t=0 output (already written)
                    }
                }
                CP_COMMIT();
                gctr++;
            }

            // ---- cell epilogue: all 4 gates in-register ----
#pragma unroll
            for (int m = 0; m < 2; m++)
#pragma unroll
                for (int s2 = 0; s2 < 2; s2++)
#pragma unroll
                    for (int q = 0; q < 2; q++)
#pragma unroll
                        for (int d = 0; d < 2; d++) {
                            int r  = wm * 32 + m * 16 + q * 8 + g;
                            int j  = wn * 16 + s2 * 8 + t4 * 2 + d;
                            int cr = q * 2 + d;
                            float gi = acc[m][0 + s2][cr] + bs[j];
                            float gf = acc[m][2 + s2][cr] + bs[128 + j];
                            float gg = acc[m][4 + s2][cr] + bs[256 + j];
                            float go = acc[m][6 + s2][cr] + bs[384 + j];
                            int ci = m * 8 + s2 * 4 + q * 2 + d;
                            float cold = Cs[ci * 512 + tid];
                            float cn = sigf(gf) * cold + sigf(gi) * tanh_fast(gg);
                            float h  = sigf(go) * tanh_fast(cn);
                            Cs[ci * 512 + tid] = cn;
                            unsigned hw = f2tf(h);
                            Hs[wn * 1280 + r * 20 + (j & 15)] = hw;
                            Xout[((size_t)t * BATCH + row0 + r) * 128 + j] = hw;
                        }
            // next t's chunk-0 barrier orders these writes before any reader
        }
        // ---- layer transition ----
        __syncthreads();   // all epilogue reads of bs/Hs done before rewrite
        if (l + 1 < LAYERS) {
            bs[tid] = bih[(l + 1) * 512 + tid] + bhh[(l + 1) * 512 + tid];
#pragma unroll
            for (int i = 0; i < 16; i++) Cs[i * 512 + tid] = 0.f;
            for (int i = tid; i < 8 * 64 * 20; i += 512) Hs[i] = 0;
            Xin  = Xout;
            Xout = (Xout == Xa) ? Xb : Xa;
        }
    }
    CP_WAIT0();
}

// ---------------- fc_out: fc = Y @ W^T + b, fused scatter (Y is tf32 words) ----------------
__global__ void __launch_bounds__(256) k_fcout(const unsigned* __restrict__ Y,
                                               const float* __restrict__ W,
                                               const float* __restrict__ bias,
                                               float* __restrict__ pred,
                                               float* __restrict__ plog) {
    __shared__ unsigned As[128][20];
    __shared__ unsigned Bs[80][20];
    const int tid  = threadIdx.x;
    const int lane = tid & 31;
    const int wm   = tid >> 5;
    const int row0 = blockIdx.x * 128;
    const int g    = lane >> 2;
    const int t4   = lane & 3;

    float acc[10][4];
#pragma unroll
    for (int i = 0; i < 10; i++)
#pragma unroll
        for (int j = 0; j < 4; j++) acc[i][j] = 0.f;

    for (int kc = 0; kc < 8; kc++) {
        const int k0 = kc * 16;
#pragma unroll
        for (int i = 0; i < 2; i++) {
            int idx = tid + i * 256;
            int m = idx >> 2, kv = idx & 3;
            uint4 v = *(const uint4*)(Y + (size_t)(row0 + m) * HID + k0 + kv * 4);
            *(uint4*)&As[m][kv * 4] = v;
        }
#pragma unroll
        for (int i = 0; i < 2; i++) {
            int idx = tid + i * 256;
            if (idx < 320) {
                int n = idx >> 2, kv = idx & 3;
                float4 v = make_float4(0.f, 0.f, 0.f, 0.f);
                if (n < 75) v = *(const float4*)(W + (size_t)n * HID + k0 + kv * 4);
                *(uint4*)&Bs[n][kv * 4] = tf4(v);
            }
        }
        __syncthreads();
#pragma unroll
        for (int ks = 0; ks < 2; ks++) {
            const int kb = ks * 8;
            unsigned a0 = As[wm * 16 + g][kb + t4];
            unsigned a1 = As[wm * 16 + g + 8][kb + t4];
            unsigned a2 = As[wm * 16 + g][kb + t4 + 4];
            unsigned a3 = As[wm * 16 + g + 8][kb + t4 + 4];
#pragma unroll
            for (int nt = 0; nt < 10; nt++) {
                int col = nt * 8 + g;
                unsigned b0 = Bs[col][kb + t4];
                unsigned b1 = Bs[col][kb + t4 + 4];
                mma_tf32(acc[nt], a0, a1, a2, a3, b0, b1);
            }
        }
        __syncthreads();
    }
#pragma unroll
    for (int nt = 0; nt < 10; nt++)
#pragma unroll
        for (int cr = 0; cr < 4; cr++) {
            int col = nt * 8 + t4 * 2 + (cr & 1);
            if (col >= 75) continue;
            int r = row0 + wm * 16 + g + (cr >> 1) * 8;
            int t = r >> 13;
            int b = r & (BATCH - 1);
            float v = acc[nt][cr] + bias[col];
            if (col < 50) {
                int m = col >> 1, d = col & 1;
                pred[b * (NMODES * TT * 2) + m * (TT * 2) + t * 2 + d] = v;
            } else if (t == TT - 1) {
                plog[b * NMODES + (col - 50)] = v;
            }
        }
}

// ---------------- softmax over 25 modes ----------------
__global__ void __launch_bounds__(256) k_softmax(const float* __restrict__ plog,
                                                 float* __restrict__ out) {
    int b = blockIdx.x * blockDim.x + threadIdx.x;
    if (b >= BATCH) return;
    float v[NMODES];
    float m = -1e30f;
#pragma unroll
    for (int j = 0; j < NMODES; j++) {
        v[j] = plog[b * NMODES + j];
        m = fmaxf(m, v[j]);
    }
    float s = 0.f;
#pragma unroll
    for (int j = 0; j < NMODES; j++) {
        v[j] = __expf(v[j] - m);
        s += v[j];
    }
    float inv = __fdividef(1.f, s);
#pragma unroll
    for (int j = 0; j < NMODES; j++) out[b * NMODES + j] = v[j] * inv;
}

// ---------------- launcher ----------------
extern "C" void kernel_launch(void* const* d_in, const int* in_sizes, int n_in,
                              void* d_out, int out_size) {
    const float* backbone = (const float*)d_in[0];
    const float* fcW      = (const float*)d_in[1];
    const float* fcb      = (const float*)d_in[2];
    const float* Wih      = (const float*)d_in[3];
    const float* Whh      = (const float*)d_in[4];
    const float* bih      = (const float*)d_in[5];
    const float* bhh      = (const float*)d_in[6];
    const float* foW      = (const float*)d_in[7];
    const float* fob      = (const float*)d_in[8];

    float* out  = (float*)d_out;
    float* pred = out;
    float* prob = out + (size_t)BATCH * NMODES * TT * 2;

    unsigned *encp, *pXa, *pXb, *wp;
    float* plogb;
    cudaGetSymbolAddress((void**)&encp,  g_encp);
    cudaGetSymbolAddress((void**)&pXa,   g_Xa);
    cudaGetSymbolAddress((void**)&pXb,   g_Xb);
    cudaGetSymbolAddress((void**)&wp,    g_Wp);
    cudaGetSymbolAddress((void**)&plogb, g_plog);

    cudaFuncSetAttribute(k_lstm, cudaFuncAttributeMaxDynamicSharedMemorySize, SMEM_BYTES);

    k_pack<<<(LAYERS * 16 * 512 * 16 + 255) / 256, 256>>>(Wih, Whh, wp);
    k_fcin<<<BATCH / 64, 256>>>(backbone, fcW, fcb, encp);
    k_lstm<<<BATCH / 64, 512, SMEM_BYTES>>>(encp, wp, bih, bhh, pXa, pXb);
    // LAYERS = 10 (even): final output lives in g_Xb
    k_fcout<<<(TT * BATCH) / 128, 256>>>(pXb, foW, fob, pred, plogb);
    k_softmax<<<BATCH / 256, 256>>>(plogb, prob);
}

// round 11
// speedup vs baseline: 1.7390x; 1.1342x over previous
#include <cuda_runtime.h>
#include <cuda_bf16.h>

#define BATCH   8192
#define HID     128
#define TT      12
#define LAYERS  10
#define G4      512
#define ENCL    4096
#define NMODES  25

// ---------------- scratch (static device globals; no allocation) ----------------
__device__ unsigned g_encp[BATCH * HID];                 // enc, tf32 words, granule-permuted
__device__ unsigned g_Xa  [TT * BATCH * HID];            // inter-layer x (tf32, permuted)
__device__ unsigned g_Xb  [TT * BATCH * HID];
__device__ unsigned g_Wp  [LAYERS * 16 * 512 * 16];      // packed tf32 weights, granule layout
__device__ float    g_plog[BATCH * NMODES];

// ---------------- helpers ----------------
__device__ __forceinline__ unsigned f2tf(float x) {
    unsigned u;
    asm("cvt.rna.tf32.f32 %0, %1;" : "=r"(u) : "f"(x));
    return u;
}
__device__ __forceinline__ void mma_tf32(float c[4],
                                         unsigned a0, unsigned a1, unsigned a2, unsigned a3,
                                         unsigned b0, unsigned b1) {
    asm volatile(
        "mma.sync.aligned.m16n8k8.row.col.f32.tf32.tf32.f32 "
        "{%0,%1,%2,%3}, {%4,%5,%6,%7}, {%8,%9}, {%0,%1,%2,%3};\n"
        : "+f"(c[0]), "+f"(c[1]), "+f"(c[2]), "+f"(c[3])
        : "r"(a0), "r"(a1), "r"(a2), "r"(a3), "r"(b0), "r"(b1));
}
__device__ __forceinline__ float sigf(float x) { return __fdividef(1.f, 1.f + __expf(-x)); }
__device__ __forceinline__ float tanh_fast(float x) { return __fdividef(2.f, 1.f + __expf(-2.f * x)) - 1.f; }

__device__ __forceinline__ void cp16(unsigned* dst_smem, const unsigned* src) {
    unsigned d = (unsigned)__cvta_generic_to_shared(dst_smem);
    asm volatile("cp.async.cg.shared.global [%0], [%1], 16;\n" :: "r"(d), "l"(src));
}
#define CP_COMMIT() asm volatile("cp.async.commit_group;\n" ::: "memory")
#define CP_WAIT(N)  asm volatile("cp.async.wait_group %0;\n" :: "n"(N) : "memory")

// Granule layout within each 16-word (row, 16k) line:
//   logical granule q = ks*4 + t4 holds words (k = ks*8+t4, k = ks*8+t4+4)
//   storage granule  = q ^ (4 * ((line_index>>1)&1))   [line_index = row or col]
// -> LDS.64 fragment loads are conflict-free at stride 16 (no padding).

// ---------------- weight pre-pack ----------------
__global__ void __launch_bounds__(256) k_pack(const float* __restrict__ Wih,
                                              const float* __restrict__ Whh,
                                              unsigned* __restrict__ Wp) {
    int idx = blockIdx.x * 256 + threadIdx.x;
    if (idx >= LAYERS * 16 * 512 * 16) return;
    int wst = idx & 15;
    int c   = (idx >> 4) & 511;
    int kc  = (idx >> 13) & 15;
    int l   = idx >> 17;
    int qst = wst >> 1, half = wst & 1;
    int qlog = qst ^ (((c >> 1) & 1) << 2);
    int kk = (kc & 7) * 16 + (qlog >> 2) * 8 + (qlog & 3) + half * 4;
    float v = (kc < 8) ? Wih[((size_t)l * 512 + c) * 128 + kk]
                       : Whh[((size_t)l * 512 + c) * 128 + kk];
    Wp[idx] = f2tf(v);
}

// ---------------- fc_in: enc = tf32(relu(backbone @ W^T + b)), cp.async 3-buf ----------------
__global__ void __launch_bounds__(256) k_fcin(const float* __restrict__ A,
                                              const float* __restrict__ W,
                                              const float* __restrict__ bias,
                                              unsigned* __restrict__ out) {
    __shared__ unsigned smf[3 * 3840];          // per buf: As 64*20, Bs 128*20
    const int tid  = threadIdx.x;
    const int lane = tid & 31;
    const int w    = tid >> 5;
    const int wm   = w & 3;
    const int wn   = w >> 2;
    const int row0 = blockIdx.x * 64;
    const int g    = lane >> 2;
    const int t4   = lane & 3;
    const int sbit = (g >> 1) & 1;

    float acc[8][4];
#pragma unroll
    for (int i = 0; i < 8; i++)
#pragma unroll
        for (int j = 0; j < 4; j++) acc[i][j] = 0.f;

    auto issue = [&](int kc) {
        unsigned* As = smf + (kc % 3) * 3840;
        unsigned* Bs = As + 1280;
        const int k0 = kc * 16;
        {   // A: 256 x 16B
            int m = tid >> 2, kv = tid & 3;
            cp16(As + m * 20 + kv * 4, (const unsigned*)(A + (size_t)(row0 + m) * ENCL + k0 + kv * 4));
        }
#pragma unroll
        for (int i = 0; i < 2; i++) {   // B: 512 x 16B
            int idx = tid + i * 256;
            int n = idx >> 2, kv = idx & 3;
            cp16(Bs + n * 20 + kv * 4, (const unsigned*)(W + (size_t)n * ENCL + k0 + kv * 4));
        }
    };

    issue(0); CP_COMMIT();
    issue(1); CP_COMMIT();

    for (int kc = 0; kc < ENCL / 16; kc++) {
        CP_WAIT(1);
        __syncthreads();
        if (kc + 2 < ENCL / 16) issue(kc + 2);
        CP_COMMIT();
        const unsigned* As = smf + (kc % 3) * 3840;
        const unsigned* Bs = As + 1280;
#pragma unroll
        for (int ks = 0; ks < 2; ks++) {
            const int kb = ks * 8;
            unsigned a0 = As[(wm * 16 + g) * 20 + kb + t4];
            unsigned a1 = As[(wm * 16 + g + 8) * 20 + kb + t4];
            unsigned a2 = As[(wm * 16 + g) * 20 + kb + t4 + 4];
            unsigned a3 = As[(wm * 16 + g + 8) * 20 + kb + t4 + 4];
#pragma unroll
            for (int nt = 0; nt < 8; nt++) {
                int col = wn * 64 + nt * 8 + g;
                unsigned b0 = Bs[col * 20 + kb + t4];
                unsigned b1 = Bs[col * 20 + kb + t4 + 4];
                mma_tf32(acc[nt], a0, a1, a2, a3, b0, b1);
            }
        }
    }
    // epilogue: bias + relu, write tf32 in granule-permuted layout
#pragma unroll
    for (int nt = 0; nt < 8; nt++)
#pragma unroll
        for (int cr = 0; cr < 4; cr++) {
            int r   = row0 + wm * 16 + g + (cr >> 1) * 8;
            int col = wn * 64 + nt * 8 + t4 * 2 + (cr & 1);
            float v = fmaxf(acc[nt][cr] + bias[col], 0.f);
            int wl = col & 15;
            int rem = wl & 7;
            int qlog = (wl >> 3) * 4 + (rem & 3);
            int half = rem >> 2;
            int wst = ((qlog ^ (sbit << 2)) << 1) + half;
            out[(size_t)r * 128 + (col >> 4) * 16 + wst] = f2tf(v);
        }
}

// ---------------- persistent fused LSTM ----------------
// 128 CTAs x 512 thr (16 warps: wm 0..1 = 32-row half, wn 0..7 = 16-col strip x 4 gates).
// Smem (words): Bs 4 bufs x 512x16 = 32768 | Xs 8192 | Hs 8192 | bias 512
#define OFF_XS   32768
#define OFF_HS   40960
#define OFF_BIAS 49152
#define SMEM_BYTES ((49152 + 512) * 4)   // 198656

__global__ void __launch_bounds__(512, 1) k_lstm(const unsigned* __restrict__ enc,
                                                 const unsigned* __restrict__ Wp,
                                                 const float* __restrict__ bih,
                                                 const float* __restrict__ bhh,
                                                 unsigned* __restrict__ Xa,
                                                 unsigned* __restrict__ Xb) {
    extern __shared__ unsigned sm[];
    unsigned* Bs = sm;
    unsigned* Xs = sm + OFF_XS;
    unsigned* Hs = sm + OFF_HS;
    float*    bs = (float*)(sm + OFF_BIAS);

    const int tid  = threadIdx.x;
    const int lane = tid & 31;
    const int w    = tid >> 5;
    const int wm   = w & 1;
    const int wn   = w >> 1;
    const int g    = lane >> 2;
    const int t4   = lane & 3;
    const int sbit = (g >> 1) & 1;
    const int woff0 = sbit * 8 + t4 * 2;     // ks=0 word offset (granule-swizzled)
    const int woff1 = woff0 ^ 8;             // ks=1
    const int row0 = blockIdx.x * 64;

    float creg[16];
#pragma unroll
    for (int i = 0; i < 16; i++) creg[i] = 0.f;

    // ---- init ----
    bs[tid] = bih[tid] + bhh[tid];
    for (int i = tid; i < 8192; i += 512) Hs[i] = 0;
    for (int idx = tid; idx < 2048; idx += 512) {   // Xs <- enc (layer-0 x, t-invariant)
        int r = (idx >> 2) & 63, kcb = idx >> 8, gp = idx & 3;
        *(uint4*)&Xs[idx * 4] = *(const uint4*)&enc[(size_t)(row0 + r) * 128 + kcb * 16 + gp * 4];
    }
    __syncthreads();

    auto issueB = [&](int gn) {
        const unsigned* src = Wp + (((size_t)(gn / 192) * 16 + (gn & 15)) << 13);
        unsigned* dst = Bs + (size_t)(gn & 3) * 8192;
#pragma unroll
        for (int i = 0; i < 4; i++) {
            int idx = i * 512 + tid;
            cp16(dst + idx * 4, src + idx * 4);
        }
    };
    auto issueX = [&](const unsigned* srcT) {
#pragma unroll
        for (int i = 0; i < 4; i++) {
            int idx = i * 512 + tid;
            int r = (idx >> 2) & 63, kcb = idx >> 8, gp = idx & 3;
            cp16(Xs + idx * 4, srcT + (size_t)(row0 + r) * 128 + kcb * 16 + gp * 4);
        }
    };

    issueB(0); CP_COMMIT();
    issueB(1); CP_COMMIT();
    issueB(2); CP_COMMIT();

    const unsigned* Xin = Xa;
    unsigned*       Xout = Xa;
    float acc[2][8][4];
    int gctr = 0;

    for (int l = 0; l < LAYERS; l++) {
        for (int t = 0; t < TT; t++) {
#pragma unroll
            for (int a = 0; a < 2; a++)
#pragma unroll
                for (int b = 0; b < 8; b++)
#pragma unroll
                    for (int q = 0; q < 4; q++) acc[a][b][q] = 0.f;

            for (int kc = 0; kc < 16; kc++) {
                CP_WAIT(2);                 // group gctr landed
                __syncthreads();            // all warps done reading slot (gctr-1)
                int gn = gctr + 3;
                if (gn < LAYERS * 192) issueB(gn);
                if (kc == 8) {              // Xs free now (chunks 0-7 consumed)
                    if (t < TT - 1) { if (l > 0) issueX(Xin + (size_t)(t + 1) * BATCH * 128); }
                    else if (l < LAYERS - 1) issueX(Xout);   // (l+1, t=0) input
                }
                CP_COMMIT();

                const unsigned* Bb   = Bs + (size_t)(gctr & 3) * 8192;
                const unsigned* Asrc = (kc < 8) ? (Xs + kc * 1024) : (Hs + (kc - 8) * 1024);
#pragma unroll
                for (int ks = 0; ks < 2; ks++) {
                    const int woff = ks ? woff1 : woff0;
                    uint2 A0 = *(const uint2*)&Asrc[(wm * 32 + g) * 16 + woff];
                    uint2 A1 = *(const uint2*)&Asrc[(wm * 32 + g + 8) * 16 + woff];
                    uint2 A2 = *(const uint2*)&Asrc[(wm * 32 + 16 + g) * 16 + woff];
                    uint2 A3 = *(const uint2*)&Asrc[(wm * 32 + 24 + g) * 16 + woff];
#pragma unroll
                    for (int nf = 0; nf < 8; nf++) {
                        int col = (nf >> 1) * 128 + wn * 16 + (nf & 1) * 8 + g;
                        uint2 Bv = *(const uint2*)&Bb[col * 16 + woff];
                        mma_tf32(acc[0][nf], A0.x, A1.x, A0.y, A1.y, Bv.x, Bv.y);
                        mma_tf32(acc[1][nf], A2.x, A3.x, A2.y, A3.y, Bv.x, Bv.y);
                    }
                }
                gctr++;
            }

            // ---- cell epilogue (4 gates + c in registers) ----
            __syncthreads();               // all chunk-15 Hs reads done
#pragma unroll
            for (int m = 0; m < 2; m++)
#pragma unroll
                for (int s2 = 0; s2 < 2; s2++)
#pragma unroll
                    for (int q = 0; q < 2; q++)
#pragma unroll
                        for (int d = 0; d < 2; d++) {
                            int cr = q * 2 + d;
                            int r  = wm * 32 + m * 16 + q * 8 + g;
                            int j  = wn * 16 + s2 * 8 + t4 * 2 + d;
                            float gi = acc[m][0 + s2][cr] + bs[j];
                            float gf = acc[m][2 + s2][cr] + bs[128 + j];
                            float gg = acc[m][4 + s2][cr] + bs[256 + j];
                            float go = acc[m][6 + s2][cr] + bs[384 + j];
                            int ci = ((m * 2 + s2) * 2 + q) * 2 + d;
                            float cn = sigf(gf) * creg[ci] + sigf(gi) * tanh_fast(gg);
                            float h  = sigf(go) * tanh_fast(cn);
                            creg[ci] = cn;
                            int rem  = t4 * 2 + d;
                            int qlog = s2 * 4 + (rem & 3);
                            int wst  = ((qlog ^ (sbit << 2)) << 1) + (rem >> 2);
                            Hs[wn * 1024 + r * 16 + wst] = f2tf(h);
                        }
            __syncthreads();               // Hs complete
            // coalesced h -> global (storage order = global order)
#pragma unroll
            for (int i = 0; i < 4; i++) {
                int idx = i * 512 + tid;
                int r = (idx >> 2) & 63, kcb = idx >> 8, gp = idx & 3;
                *(uint4*)&Xout[((size_t)t * BATCH + row0 + r) * 128 + kcb * 16 + gp * 4] =
                    *(const uint4*)&Hs[idx * 4];
            }

            if (t == TT - 1) {             // layer transition
                __syncthreads();           // copy reads of Hs done
                if (l + 1 < LAYERS) {
                    bs[tid] = bih[(l + 1) * 512 + tid] + bhh[(l + 1) * 512 + tid];
                    for (int i = tid; i < 8192; i += 512) Hs[i] = 0;
#pragma unroll
                    for (int i = 0; i < 16; i++) creg[i] = 0.f;
                    Xin  = Xout;
                    Xout = (Xout == Xa) ? Xb : Xa;
                }
            }
        }
    }
    CP_WAIT(0);
}

// ---------------- fc_out: Y (granule layout) @ W^T + b, fused scatter ----------------
__global__ void __launch_bounds__(256) k_fcout(const unsigned* __restrict__ Y,
                                               const float* __restrict__ W,
                                               const float* __restrict__ bias,
                                               float* __restrict__ pred,
                                               float* __restrict__ plog) {
    __shared__ unsigned As[128 * 16];
    __shared__ unsigned Bsm[80 * 16];
    const int tid  = threadIdx.x;
    const int lane = tid & 31;
    const int wm   = tid >> 5;
    const int row0 = blockIdx.x * 128;
    const int g    = lane >> 2;
    const int t4   = lane & 3;
    const int sbit = (g >> 1) & 1;
    const int woff0 = sbit * 8 + t4 * 2;
    const int woff1 = woff0 ^ 8;

    float acc[10][4];
#pragma unroll
    for (int i = 0; i < 10; i++)
#pragma unroll
        for (int j = 0; j < 4; j++) acc[i][j] = 0.f;

    for (int kc = 0; kc < 8; kc++) {
        // A: straight uint4 copy (already granule-permuted)
#pragma unroll
        for (int i = 0; i < 2; i++) {
            int idx = tid + i * 256;
            int m = idx >> 2, gp = idx & 3;
            *(uint4*)&As[m * 16 + gp * 4] =
                *(const uint4*)&Y[(size_t)(row0 + m) * 128 + kc * 16 + gp * 4];
        }
        // B: fp32 -> tf32 with granule permute (rows >= 75 zero)
#pragma unroll
        for (int i = 0; i < 5; i++) {
            int idx = tid + i * 256;
            int c = idx >> 4, wst = idx & 15;
            int qst = wst >> 1, half = wst & 1;
            int qlog = qst ^ (((c >> 1) & 1) << 2);
            int kk = kc * 16 + (qlog >> 2) * 8 + (qlog & 3) + half * 4;
            float v = (c < 75) ? W[(size_t)c * 128 + kk] : 0.f;
            Bsm[c * 16 + wst] = f2tf(v);
        }
        __syncthreads();
#pragma unroll
        for (int ks = 0; ks < 2; ks++) {
            const int woff = ks ? woff1 : woff0;
            uint2 Alo = *(const uint2*)&As[(wm * 16 + g) * 16 + woff];
            uint2 Ahi = *(const uint2*)&As[(wm * 16 + g + 8) * 16 + woff];
#pragma unroll
            for (int nt = 0; nt < 10; nt++) {
                uint2 Bv = *(const uint2*)&Bsm[(nt * 8 + g) * 16 + woff];
                mma_tf32(acc[nt], Alo.x, Ahi.x, Alo.y, Ahi.y, Bv.x, Bv.y);
            }
        }
        __syncthreads();
    }
#pragma unroll
    for (int nt = 0; nt < 10; nt++)
#pragma unroll
        for (int cr = 0; cr < 4; cr++) {
            int col = nt * 8 + t4 * 2 + (cr & 1);
            if (col >= 75) continue;
            int r = row0 + wm * 16 + g + (cr >> 1) * 8;
            int t = r >> 13;
            int b = r & (BATCH - 1);
            float v = acc[nt][cr] + bias[col];
            if (col < 50) {
                int m = col >> 1, d = col & 1;
                pred[b * (NMODES * TT * 2) + m * (TT * 2) + t * 2 + d] = v;
            } else if (t == TT - 1) {
                plog[b * NMODES + (col - 50)] = v;
            }
        }
}

// ---------------- softmax over 25 modes ----------------
__global__ void __launch_bounds__(256) k_softmax(const float* __restrict__ plog,
                                                 float* __restrict__ out) {
    int b = blockIdx.x * blockDim.x + threadIdx.x;
    if (b >= BATCH) return;
    float v[NMODES];
    float m = -1e30f;
#pragma unroll
    for (int j = 0; j < NMODES; j++) {
        v[j] = plog[b * NMODES + j];
        m = fmaxf(m, v[j]);
    }
    float s = 0.f;
#pragma unroll
    for (int j = 0; j < NMODES; j++) {
        v[j] = __expf(v[j] - m);
        s += v[j];
    }
    float inv = __fdividef(1.f, s);
#pragma unroll
    for (int j = 0; j < NMODES; j++) out[b * NMODES + j] = v[j] * inv;
}

// ---------------- launcher ----------------
extern "C" void kernel_launch(void* const* d_in, const int* in_sizes, int n_in,
                              void* d_out, int out_size) {
    const float* backbone = (const float*)d_in[0];
    const float* fcW      = (const float*)d_in[1];
    const float* fcb      = (const float*)d_in[2];
    const float* Wih      = (const float*)d_in[3];
    const float* Whh      = (const float*)d_in[4];
    const float* bih      = (const float*)d_in[5];
    const float* bhh      = (const float*)d_in[6];
    const float* foW      = (const float*)d_in[7];
    const float* fob      = (const float*)d_in[8];

    float* out  = (float*)d_out;
    float* pred = out;
    float* prob = out + (size_t)BATCH * NMODES * TT * 2;

    unsigned *encp, *pXa, *pXb, *wp;
    float* plogb;
    cudaGetSymbolAddress((void**)&encp,  g_encp);
    cudaGetSymbolAddress((void**)&pXa,   g_Xa);
    cudaGetSymbolAddress((void**)&pXb,   g_Xb);
    cudaGetSymbolAddress((void**)&wp,    g_Wp);
    cudaGetSymbolAddress((void**)&plogb, g_plog);

    cudaFuncSetAttribute(k_lstm, cudaFuncAttributeMaxDynamicSharedMemorySize, SMEM_BYTES);

    k_pack<<<(LAYERS * 16 * 512 * 16 + 255) / 256, 256>>>(Wih, Whh, wp);
    k_fcin<<<BATCH / 64, 256>>>(backbone, fcW, fcb, encp);
    k_lstm<<<BATCH / 64, 512, SMEM_BYTES>>>(encp, wp, bih, bhh, pXa, pXb);
    // LAYERS = 10 (even): final output lives in g_Xb
    k_fcout<<<(TT * BATCH) / 128, 256>>>(pXb, foW, fob, pred, plogb);
    k_softmax<<<BATCH / 256, 256>>>(plogb, prob);
}

// round 12
// speedup vs baseline: 2.5404x; 1.4608x over previous
#include <cuda_runtime.h>
#include <cuda_bf16.h>

#define BATCH   8192
#define HID     128
#define TT      12
#define LAYERS  10
#define G4      512
#define ENCL    4096
#define NMODES  25

#define NCHUNK_TOTAL 1840   // per layer: 8 (t=0) + 11*16

// ---------------- scratch (static device globals; no allocation) ----------------
__device__ unsigned g_encp[BATCH * HID];                 // enc, tf32 words, granule-permuted
__device__ unsigned g_Xa  [TT * BATCH * HID];            // inter-layer x (tf32, permuted)
__device__ unsigned g_Xb  [TT * BATCH * HID];
__device__ unsigned g_Wp  [LAYERS * 16 * 512 * 16];      // packed tf32 weights [l][kc][w][gt][c8][16]
__device__ float    g_plog[BATCH * NMODES];

// ---------------- helpers ----------------
__device__ __forceinline__ unsigned f2tf(float x) {
    unsigned u;
    asm("cvt.rna.tf32.f32 %0, %1;" : "=r"(u) : "f"(x));
    return u;
}
__device__ __forceinline__ uint4 tf4(float4 v) {
    uint4 u; u.x = f2tf(v.x); u.y = f2tf(v.y); u.z = f2tf(v.z); u.w = f2tf(v.w);
    return u;
}
__device__ __forceinline__ void mma_tf32(float c[4],
                                         unsigned a0, unsigned a1, unsigned a2, unsigned a3,
                                         unsigned b0, unsigned b1) {
    asm volatile(
        "mma.sync.aligned.m16n8k8.row.col.f32.tf32.tf32.f32 "
        "{%0,%1,%2,%3}, {%4,%5,%6,%7}, {%8,%9}, {%0,%1,%2,%3};\n"
        : "+f"(c[0]), "+f"(c[1]), "+f"(c[2]), "+f"(c[3])
        : "r"(a0), "r"(a1), "r"(a2), "r"(a3), "r"(b0), "r"(b1));
}
__device__ __forceinline__ float sigf(float x) { return __fdividef(1.f, 1.f + __expf(-x)); }
__device__ __forceinline__ float tanh_fast(float x) { return __fdividef(2.f, 1.f + __expf(-2.f * x)) - 1.f; }

__device__ __forceinline__ void cp16(unsigned* dst_smem, const unsigned* src) {
    unsigned d = (unsigned)__cvta_generic_to_shared(dst_smem);
    asm volatile("cp.async.cg.shared.global [%0], [%1], 16;\n" :: "r"(d), "l"(src));
}
#define CP_COMMIT() asm volatile("cp.async.commit_group;\n" ::: "memory")
#define CP_WAIT(N)  asm volatile("cp.async.wait_group %0;\n" :: "n"(N) : "memory")

// Granule layout within each 16-word (line, 16k) group:
//   logical granule q = ks*4 + t4 holds words (k = ks*8+t4, k = ks*8+t4+4)
//   storage granule  = q ^ (4 * ((line>>1)&1))
// -> LDS.64 fragment loads are conflict-free at stride 16.

// ---------------- weight pre-pack: [l][kc][w][gt][c8][16w] ----------------
__global__ void __launch_bounds__(256) k_pack(const float* __restrict__ Wih,
                                              const float* __restrict__ Whh,
                                              unsigned* __restrict__ Wp) {
    int idx = blockIdx.x * 256 + threadIdx.x;
    if (idx >= LAYERS * 16 * 512 * 16) return;
    int wst = idx & 15;
    int c8  = (idx >> 4) & 7;
    int gt  = (idx >> 7) & 3;
    int w   = (idx >> 9) & 15;
    int kc  = (idx >> 13) & 15;
    int l   = idx >> 17;
    int col = gt * 128 + w * 8 + c8;
    int qst = wst >> 1, half = wst & 1;
    int qlog = qst ^ (((col >> 1) & 1) << 2);
    int kk = (kc & 7) * 16 + (qlog >> 2) * 8 + (qlog & 3) + half * 4;
    float v = (kc < 8) ? Wih[((size_t)l * 512 + col) * 128 + kk]
                       : Whh[((size_t)l * 512 + col) * 128 + kk];
    Wp[idx] = f2tf(v);
}

// ---------------- fc_in: enc = tf32(relu(backbone @ W^T + b)), cp.async 3-buf ----------------
__global__ void __launch_bounds__(256) k_fcin(const float* __restrict__ A,
                                              const float* __restrict__ W,
                                              const float* __restrict__ bias,
                                              unsigned* __restrict__ out) {
    __shared__ unsigned smf[3 * 3840];          // per buf: As 64*20, Bs 128*20
    const int tid  = threadIdx.x;
    const int lane = tid & 31;
    const int w    = tid >> 5;
    const int wm   = w & 3;
    const int wn   = w >> 2;
    const int row0 = blockIdx.x * 64;
    const int g    = lane >> 2;
    const int t4   = lane & 3;
    const int sbit = (g >> 1) & 1;

    float acc[8][4];
#pragma unroll
    for (int i = 0; i < 8; i++)
#pragma unroll
        for (int j = 0; j < 4; j++) acc[i][j] = 0.f;

    auto issue = [&](int kc) {
        unsigned* As = smf + (kc % 3) * 3840;
        unsigned* Bs = As + 1280;
        const int k0 = kc * 16;
        {
            int m = tid >> 2, kv = tid & 3;
            cp16(As + m * 20 + kv * 4, (const unsigned*)(A + (size_t)(row0 + m) * ENCL + k0 + kv * 4));
        }
#pragma unroll
        for (int i = 0; i < 2; i++) {
            int idx = tid + i * 256;
            int n = idx >> 2, kv = idx & 3;
            cp16(Bs + n * 20 + kv * 4, (const unsigned*)(W + (size_t)n * ENCL + k0 + kv * 4));
        }
    };

    issue(0); CP_COMMIT();
    issue(1); CP_COMMIT();

    for (int kc = 0; kc < ENCL / 16; kc++) {
        CP_WAIT(1);
        __syncthreads();
        if (kc + 2 < ENCL / 16) issue(kc + 2);
        CP_COMMIT();
        const unsigned* As = smf + (kc % 3) * 3840;
        const unsigned* Bs = As + 1280;
#pragma unroll
        for (int ks = 0; ks < 2; ks++) {
            const int kb = ks * 8;
            unsigned a0 = As[(wm * 16 + g) * 20 + kb + t4];
            unsigned a1 = As[(wm * 16 + g + 8) * 20 + kb + t4];
            unsigned a2 = As[(wm * 16 + g) * 20 + kb + t4 + 4];
            unsigned a3 = As[(wm * 16 + g + 8) * 20 + kb + t4 + 4];
#pragma unroll
            for (int nt = 0; nt < 8; nt++) {
                int col = wn * 64 + nt * 8 + g;
                unsigned b0 = Bs[col * 20 + kb + t4];
                unsigned b1 = Bs[col * 20 + kb + t4 + 4];
                mma_tf32(acc[nt], a0, a1, a2, a3, b0, b1);
            }
        }
    }
#pragma unroll
    for (int nt = 0; nt < 8; nt++)
#pragma unroll
        for (int cr = 0; cr < 4; cr++) {
            int r   = row0 + wm * 16 + g + (cr >> 1) * 8;
            int col = wn * 64 + nt * 8 + t4 * 2 + (cr & 1);
            float v = fmaxf(acc[nt][cr] + bias[col], 0.f);
            int wl = col & 15;
            int rem = wl & 7;
            int qlog = (wl >> 3) * 4 + (rem & 3);
            int half = rem >> 2;
            int wst = ((qlog ^ (sbit << 2)) << 1) + half;
            out[(size_t)r * 128 + (col >> 4) * 16 + wst] = f2tf(v);
        }
}

// ---------------- persistent fused LSTM, barrier-free chunk loop ----------------
// 128 CTAs x 512 thr. Warp w (0..15) owns cols {gt*128 + w*8 + 0..7}, M=64.
// Smem (words): Bs 16 warps x 4 slots x 512 | Xs 2 x 8192 | Hs 8192 | bias 512
#define OFF_XS   32768
#define OFF_HS   49152
#define OFF_BIAS 57344
#define SMEM_BYTES ((57344 + 512) * 4)   // 231424

__global__ void __launch_bounds__(512, 1) k_lstm(const unsigned* __restrict__ enc,
                                                 const unsigned* __restrict__ Wp,
                                                 const float* __restrict__ bih,
                                                 const float* __restrict__ bhh,
                                                 unsigned* __restrict__ Xa,
                                                 unsigned* __restrict__ Xb) {
    extern __shared__ unsigned sm[];
    unsigned* Bs = sm;
    unsigned* Xsb = sm + OFF_XS;
    unsigned* Hs = sm + OFF_HS;
    float*    bs = (float*)(sm + OFF_BIAS);

    const int tid  = threadIdx.x;
    const int lane = tid & 31;
    const int w    = tid >> 5;
    const int g    = lane >> 2;
    const int t4   = lane & 3;
    const int sbit = (g >> 1) & 1;
    const int woff0 = sbit * 8 + t4 * 2;
    const int woff1 = woff0 ^ 8;
    const int row0 = blockIdx.x * 64;
    unsigned* Bw = Bs + w * 2048;          // this warp's private 4-slot region

    float creg[16];
#pragma unroll
    for (int i = 0; i < 16; i++) creg[i] = 0.f;

    // ---- init ----
    bs[tid] = bih[tid] + bhh[tid];
    for (int idx = tid; idx < 2048; idx += 512) {   // Xs[0] <- enc
        int r = (idx >> 2) & 63, kcb = idx >> 8, gp = idx & 3;
        *(uint4*)&Xsb[idx * 4] = *(const uint4*)&enc[(size_t)(row0 + r) * 128 + kcb * 16 + gp * 4];
    }
    __syncthreads();

    // warp-private weight chunk issue: consumption index n -> (l', kc')
    auto issueB = [&](int n) {
        int lq = n / 184;
        int rq = n - lq * 184;
        int kcq = (rq < 8) ? rq : ((rq - 8) & 15);
        const unsigned* src = Wp + (((size_t)(lq * 16 + kcq) * 16 + w) << 9);
        unsigned* dst = Bw + (n & 3) * 512;
#pragma unroll
        for (int i = 0; i < 4; i++) {
            int off = i * 128 + lane * 4;
            cp16(dst + off, src + off);
        }
    };
    auto issueX = [&](const unsigned* srcT, int xb) {   // warp's 1/16 slice of next x tile
#pragma unroll
        for (int i = 0; i < 4; i++) {
            int idx = w * 128 + i * 32 + lane;
            int r = (idx >> 2) & 63, kcb = idx >> 8, gp = idx & 3;
            cp16(Xsb + xb * 8192 + idx * 4, srcT + (size_t)(row0 + r) * 128 + kcb * 16 + gp * 4);
        }
    };

    issueB(0); CP_COMMIT();
    issueB(1); CP_COMMIT();
    issueB(2); CP_COMMIT();

    const unsigned* Xin = Xa;
    unsigned*       Xout = Xa;
    float acc[4][4][4];
    int n = 0;          // weight chunk consumption counter
    int xbuf = 0;

    for (int l = 0; l < LAYERS; l++) {
        for (int t = 0; t < TT; t++) {
#pragma unroll
            for (int a = 0; a < 4; a++)
#pragma unroll
                for (int b = 0; b < 4; b++)
#pragma unroll
                    for (int q = 0; q < 4; q++) acc[a][b][q] = 0.f;

            const int nkc  = (t == 0) ? 8 : 16;
            const int trig = (t == 0) ? 3 : 7;
            const bool needX = (t < TT - 1) ? (l > 0) : (l < LAYERS - 1);
            const unsigned* xsrc = (t < TT - 1) ? (Xin + (size_t)(t + 1) * BATCH * 128) : Xout;

            for (int kc = 0; kc < nkc; kc++) {
                CP_WAIT(2);                          // warp-private: slot n&3 landed
                const unsigned* Bb   = Bw + (n & 3) * 512;
                const unsigned* Asrc = (kc < 8) ? (Xsb + xbuf * 8192 + kc * 1024)
                                                : (Hs + (kc - 8) * 1024);
#pragma unroll
                for (int ks = 0; ks < 2; ks++) {
                    const int woff = ks ? woff1 : woff0;
                    uint2 Af[8];
#pragma unroll
                    for (int mf = 0; mf < 4; mf++) {
                        Af[mf * 2]     = *(const uint2*)&Asrc[(mf * 16 + g) * 16 + woff];
                        Af[mf * 2 + 1] = *(const uint2*)&Asrc[(mf * 16 + 8 + g) * 16 + woff];
                    }
#pragma unroll
                    for (int gt = 0; gt < 4; gt++) {
                        uint2 Bv = *(const uint2*)&Bb[(gt * 8 + g) * 16 + woff];
#pragma unroll
                        for (int mf = 0; mf < 4; mf++)
                            mma_tf32(acc[mf][gt], Af[mf * 2].x, Af[mf * 2 + 1].x,
                                     Af[mf * 2].y, Af[mf * 2 + 1].y, Bv.x, Bv.y);
                    }
                }
                if (kc == trig && needX) { issueX(xsrc, xbuf ^ 1); CP_COMMIT(); }
                int gn = n + 3;
                if (gn < NCHUNK_TOTAL) { issueB(gn); CP_COMMIT(); }
                n++;
            }

            // ---- cell epilogue ----
            __syncthreads();                     // all warps done reading Hs this step
#pragma unroll
            for (int mf = 0; mf < 4; mf++)
#pragma unroll
                for (int q = 0; q < 2; q++)
#pragma unroll
                    for (int d = 0; d < 2; d++) {
                        int cr = q * 2 + d;
                        int r  = mf * 16 + q * 8 + g;
                        int j  = w * 8 + t4 * 2 + d;
                        float gi = acc[mf][0][cr] + bs[j];
                        float gf = acc[mf][1][cr] + bs[128 + j];
                        float gg = acc[mf][2][cr] + bs[256 + j];
                        float go = acc[mf][3][cr] + bs[384 + j];
                        int ci = mf * 4 + q * 2 + d;
                        float cn = sigf(gf) * creg[ci] + sigf(gi) * tanh_fast(gg);
                        float h  = sigf(go) * tanh_fast(cn);
                        creg[ci] = cn;
                        int rem  = t4 * 2 + d;
                        int qlog = (w & 1) * 4 + (rem & 3);
                        int wst  = ((qlog ^ (sbit << 2)) << 1) + (rem >> 2);
                        Hs[(w >> 1) * 1024 + r * 16 + wst] = f2tf(h);
                    }
            __syncthreads();                     // Hs complete for readers/copy
            // coalesced h -> global (storage order == global order)
#pragma unroll
            for (int i = 0; i < 4; i++) {
                int idx = i * 512 + tid;
                int r = (idx >> 2) & 63, kcb = idx >> 8, gp = idx & 3;
                *(uint4*)&Xout[((size_t)t * BATCH + row0 + r) * 128 + kcb * 16 + gp * 4] =
                    *(const uint4*)&Hs[idx * 4];
            }
            if (t == TT - 1 && l + 1 < LAYERS) { // layer transition (safe after barrier2)
                bs[tid] = bih[(l + 1) * 512 + tid] + bhh[(l + 1) * 512 + tid];
#pragma unroll
                for (int i = 0; i < 16; i++) creg[i] = 0.f;
            }
            if (needX) xbuf ^= 1;
        }
        Xin  = Xout;
        Xout = (Xout == Xa) ? Xb : Xa;
    }
    CP_WAIT(0);
}

// ---------------- fc_out: Y (granule layout) @ W^T + b, fused scatter ----------------
__global__ void __launch_bounds__(256) k_fcout(const unsigned* __restrict__ Y,
                                               const float* __restrict__ W,
                                               const float* __restrict__ bias,
                                               float* __restrict__ pred,
                                               float* __restrict__ plog) {
    __shared__ unsigned As[128 * 16];
    __shared__ unsigned Bsm[80 * 16];
    const int tid  = threadIdx.x;
    const int lane = tid & 31;
    const int wm   = tid >> 5;
    const int row0 = blockIdx.x * 128;
    const int g    = lane >> 2;
    const int t4   = lane & 3;
    const int sbit = (g >> 1) & 1;
    const int woff0 = sbit * 8 + t4 * 2;
    const int woff1 = woff0 ^ 8;

    float acc[10][4];
#pragma unroll
    for (int i = 0; i < 10; i++)
#pragma unroll
        for (int j = 0; j < 4; j++) acc[i][j] = 0.f;

    for (int kc = 0; kc < 8; kc++) {
#pragma unroll
        for (int i = 0; i < 2; i++) {
            int idx = tid + i * 256;
            int m = idx >> 2, gp = idx & 3;
            *(uint4*)&As[m * 16 + gp * 4] =
                *(const uint4*)&Y[(size_t)(row0 + m) * 128 + kc * 16 + gp * 4];
        }
#pragma unroll
        for (int i = 0; i < 5; i++) {
            int idx = tid + i * 256;
            int c = idx >> 4, wst = idx & 15;
            int qst = wst >> 1, half = wst & 1;
            int qlog = qst ^ (((c >> 1) & 1) << 2);
            int kk = kc * 16 + (qlog >> 2) * 8 + (qlog & 3) + half * 4;
            float v = (c < 75) ? W[(size_t)c * 128 + kk] : 0.f;
            Bsm[c * 16 + wst] = f2tf(v);
        }
        __syncthreads();
#pragma unroll
        for (int ks = 0; ks < 2; ks++) {
            const int woff = ks ? woff1 : woff0;
            uint2 Alo = *(const uint2*)&As[(wm * 16 + g) * 16 + woff];
            uint2 Ahi = *(const uint2*)&As[(wm * 16 + g + 8) * 16 + woff];
#pragma unroll
            for (int nt = 0; nt < 10; nt++) {
                uint2 Bv = *(const uint2*)&Bsm[(nt * 8 + g) * 16 + woff];
                mma_tf32(acc[nt], Alo.x, Ahi.x, Alo.y, Ahi.y, Bv.x, Bv.y);
            }
        }
        __syncthreads();
    }
#pragma unroll
    for (int nt = 0; nt < 10; nt++)
#pragma unroll
        for (int cr = 0; cr < 4; cr++) {
            int col = nt * 8 + t4 * 2 + (cr & 1);
            if (col >= 75) continue;
            int r = row0 + wm * 16 + g + (cr >> 1) * 8;
            int t = r >> 13;
            int b = r & (BATCH - 1);
            float v = acc[nt][cr] + bias[col];
            if (col < 50) {
                int m = col >> 1, d = col & 1;
                pred[b * (NMODES * TT * 2) + m * (TT * 2) + t * 2 + d] = v;
            } else if (t == TT - 1) {
                plog[b * NMODES + (col - 50)] = v;
            }
        }
}

// ---------------- softmax over 25 modes ----------------
__global__ void __launch_bounds__(256) k_softmax(const float* __restrict__ plog,
                                                 float* __restrict__ out) {
    int b = blockIdx.x * blockDim.x + threadIdx.x;
    if (b >= BATCH) return;
    float v[NMODES];
    float m = -1e30f;
#pragma unroll
    for (int j = 0; j < NMODES; j++) {
        v[j] = plog[b * NMODES + j];
        m = fmaxf(m, v[j]);
    }
    float s = 0.f;
#pragma unroll
    for (int j = 0; j < NMODES; j++) {
        v[j] = __expf(v[j] - m);
        s += v[j];
    }
    float inv = __fdividef(1.f, s);
#pragma unroll
    for (int j = 0; j < NMODES; j++) out[b * NMODES + j] = v[j] * inv;
}

// ---------------- launcher ----------------
extern "C" void kernel_launch(void* const* d_in, const int* in_sizes, int n_in,
                              void* d_out, int out_size) {
    const float* backbone = (const float*)d_in[0];
    const float* fcW      = (const float*)d_in[1];
    const float* fcb      = (const float*)d_in[2];
    const float* Wih      = (const float*)d_in[3];
    const float* Whh      = (const float*)d_in[4];
    const float* bih      = (const float*)d_in[5];
    const float* bhh      = (const float*)d_in[6];
    const float* foW      = (const float*)d_in[7];
    const float* fob      = (const float*)d_in[8];

    float* out  = (float*)d_out;
    float* pred = out;
    float* prob = out + (size_t)BATCH * NMODES * TT * 2;

    unsigned *encp, *pXa, *pXb, *wp;
    float* plogb;
    cudaGetSymbolAddress((void**)&encp,  g_encp);
    cudaGetSymbolAddress((void**)&pXa,   g_Xa);
    cudaGetSymbolAddress((void**)&pXb,   g_Xb);
    cudaGetSymbolAddress((void**)&wp,    g_Wp);
    cudaGetSymbolAddress((void**)&plogb, g_plog);

    cudaFuncSetAttribute(k_lstm, cudaFuncAttributeMaxDynamicSharedMemorySize, SMEM_BYTES);

    k_pack<<<(LAYERS * 16 * 512 * 16 + 255) / 256, 256>>>(Wih, Whh, wp);
    k_fcin<<<BATCH / 64, 256>>>(backbone, fcW, fcb, encp);
    k_lstm<<<BATCH / 64, 512, SMEM_BYTES>>>(encp, wp, bih, bhh, pXa, pXb);
    // LAYERS = 10 (even): final output lives in g_Xb
    k_fcout<<<(TT * BATCH) / 128, 256>>>(pXb, foW, fob, pred, plogb);
    k_softmax<<<BATCH / 256, 256>>>(plogb, prob);
}

// round 14
// speedup vs baseline: 4.1774x; 1.6444x over previous
#include <cuda_runtime.h>
#include <cuda_fp16.h>

#define BATCH   8192
#define HID     128
#define TT      12
#define LAYERS  10
#define G4      512
#define ENCL    4096
#define NMODES  25

#define NCHUNK_TOTAL 1840   // per layer: 8 (t=0) + 11*16

// ---------------- scratch (static device globals; no allocation) ----------------
__device__ __half g_encp[BATCH * HID];                  // enc, fp16, fragment-packed
__device__ __half g_Xa  [TT * BATCH * HID];             // inter-layer x (fp16, packed)
__device__ __half g_Xb  [TT * BATCH * HID];
__device__ __half g_Wp  [LAYERS * 16 * 16 * 512];       // packed fp16 weights [l][kc][w][512h]
__device__ float  g_plog[BATCH * NMODES];

// ---------------- helpers ----------------
__device__ __forceinline__ unsigned f2tf(float x) {
    unsigned u;
    asm("cvt.rna.tf32.f32 %0, %1;" : "=r"(u) : "f"(x));
    return u;
}
__device__ __forceinline__ void mma_tf32(float c[4],
                                         unsigned a0, unsigned a1, unsigned a2, unsigned a3,
                                         unsigned b0, unsigned b1) {
    asm volatile(
        "mma.sync.aligned.m16n8k8.row.col.f32.tf32.tf32.f32 "
        "{%0,%1,%2,%3}, {%4,%5,%6,%7}, {%8,%9}, {%0,%1,%2,%3};\n"
        : "+f"(c[0]), "+f"(c[1]), "+f"(c[2]), "+f"(c[3])
        : "r"(a0), "r"(a1), "r"(a2), "r"(a3), "r"(b0), "r"(b1));
}
__device__ __forceinline__ void mma_f16(float c[4],
                                        unsigned a0, unsigned a1, unsigned a2, unsigned a3,
                                        unsigned b0, unsigned b1) {
    asm volatile(
        "mma.sync.aligned.m16n8k16.row.col.f32.f16.f16.f32 "
        "{%0,%1,%2,%3}, {%4,%5,%6,%7}, {%8,%9}, {%0,%1,%2,%3};\n"
        : "+f"(c[0]), "+f"(c[1]), "+f"(c[2]), "+f"(c[3])
        : "r"(a0), "r"(a1), "r"(a2), "r"(a3), "r"(b0), "r"(b1));
}
__device__ __forceinline__ float sigf(float x) { return __fdividef(1.f, 1.f + __expf(-x)); }
__device__ __forceinline__ float tanh_fast(float x) { return __fdividef(2.f, 1.f + __expf(-2.f * x)) - 1.f; }

__device__ __forceinline__ void cp16(void* dst_smem, const void* src) {
    unsigned d = (unsigned)__cvta_generic_to_shared(dst_smem);
    asm volatile("cp.async.cg.shared.global [%0], [%1], 16;\n" :: "r"(d), "l"(src));
}
#define CP_COMMIT() asm volatile("cp.async.commit_group;\n" ::: "memory")
#define CP_WAIT(N)  asm volatile("cp.async.wait_group %0;\n" :: "n"(N) : "memory")

// ======================= fragment-packed fp16 layouts =======================
// X/H tile (64 rows x 128 cols), 8192 halfs per tile:
//   off_h = c*1024 + mf*256 + (g*4+t4)*8 + kh*4 + q*2 + d
//   where c=col>>4, t4=(col>>1)&3, kh=(col>>3)&1, d=col&1, mf=r>>4, q=(r>>3)&1, g=r&7.
//   One LDS.128 at (mf*256 + gidx*8) yields mma A regs [a0,a1,a2,a3].
// B (weights) per (l,kc,warp): 512 halfs:
//   off_h = gidx*16 + (P ^ (g&1))*8 + (gt&1)*4 + kh*2 + d    (gidx=g*4+t4, P=gt>>1)
//   One LDS.128 at (gidx*16 + (P^(g&1))*8) yields [b0(2P),b1(2P),b0(2P+1),b1(2P+1)].

__device__ __forceinline__ int xpack_off(int r6, int col) {   // r6 in [0,64), col in [0,128)
    int c = col >> 4, t4 = (col >> 1) & 3, kh = (col >> 3) & 1, d = col & 1;
    int mf = r6 >> 4, q = (r6 >> 3) & 1, g = r6 & 7;
    return c * 1024 + mf * 256 + (g * 4 + t4) * 8 + kh * 4 + q * 2 + d;
}

// ---------------- weight pre-pack ----------------
__global__ void __launch_bounds__(256) k_pack(const float* __restrict__ Wih,
                                              const float* __restrict__ Whh,
                                              __half* __restrict__ Wp) {
    int idx = blockIdx.x * 256 + threadIdx.x;
    if (idx >= LAYERS * 16 * 16 * 512) return;
    int hoff = idx & 511;
    int w    = (idx >> 9) & 15;
    int kc   = (idx >> 13) & 15;
    int l    = idx >> 17;
    int gidx = hoff >> 4, rem = hoff & 15;
    int g = gidx >> 2, t4 = gidx & 3;
    int seg = rem >> 3;
    int P = seg ^ (g & 1);
    int gt = P * 2 + ((rem >> 2) & 1);
    int kh = (rem >> 1) & 1, d = rem & 1;
    int col = gt * 128 + w * 8 + g;
    int kk  = (kc & 7) * 16 + kh * 8 + t4 * 2 + d;
    float v = (kc < 8) ? Wih[((size_t)l * 512 + col) * 128 + kk]
                       : Whh[((size_t)l * 512 + col) * 128 + kk];
    Wp[idx] = __float2half_rn(v);
}

// ---------------- fc_in: enc = fp16pack(relu(backbone @ W^T + b)), tf32 core ----------------
__global__ void __launch_bounds__(256) k_fcin(const float* __restrict__ A,
                                              const float* __restrict__ W,
                                              const float* __restrict__ bias,
                                              __half* __restrict__ out) {
    __shared__ unsigned smf[3 * 3840];          // per buf: As 64*20, Bs 128*20
    const int tid  = threadIdx.x;
    const int lane = tid & 31;
    const int w    = tid >> 5;
    const int wm   = w & 3;
    const int wn   = w >> 2;
    const int row0 = blockIdx.x * 64;
    const int g    = lane >> 2;
    const int t4   = lane & 3;

    float acc[8][4];
#pragma unroll
    for (int i = 0; i < 8; i++)
#pragma unroll
        for (int j = 0; j < 4; j++) acc[i][j] = 0.f;

    auto issue = [&](int kc) {
        unsigned* As = smf + (kc % 3) * 3840;
        unsigned* Bs = As + 1280;
        const int k0 = kc * 16;
        {
            int m = tid >> 2, kv = tid & 3;
            cp16(As + m * 20 + kv * 4, A + (size_t)(row0 + m) * ENCL + k0 + kv * 4);
        }
#pragma unroll
        for (int i = 0; i < 2; i++) {
            int idx = tid + i * 256;
            int n = idx >> 2, kv = idx & 3;
            cp16(Bs + n * 20 + kv * 4, W + (size_t)n * ENCL + k0 + kv * 4);
        }
    };

    issue(0); CP_COMMIT();
    issue(1); CP_COMMIT();

    for (int kc = 0; kc < ENCL / 16; kc++) {
        CP_WAIT(1);
        __syncthreads();
        if (kc + 2 < ENCL / 16) issue(kc + 2);
        CP_COMMIT();
        const unsigned* As = smf + (kc % 3) * 3840;
        const unsigned* Bs = As + 1280;
#pragma unroll
        for (int ks = 0; ks < 2; ks++) {
            const int kb = ks * 8;
            unsigned a0 = As[(wm * 16 + g) * 20 + kb + t4];
            unsigned a1 = As[(wm * 16 + g + 8) * 20 + kb + t4];
            unsigned a2 = As[(wm * 16 + g) * 20 + kb + t4 + 4];
            unsigned a3 = As[(wm * 16 + g + 8) * 20 + kb + t4 + 4];
#pragma unroll
            for (int nt = 0; nt < 8; nt++) {
                int col = wn * 64 + nt * 8 + g;
                unsigned b0 = Bs[col * 20 + kb + t4];
                unsigned b1 = Bs[col * 20 + kb + t4 + 4];
                mma_tf32(acc[nt], a0, a1, a2, a3, b0, b1);
            }
        }
    }
#pragma unroll
    for (int nt = 0; nt < 8; nt++)
#pragma unroll
        for (int cr = 0; cr < 4; cr++) {
            int r   = row0 + wm * 16 + g + (cr >> 1) * 8;
            int col = wn * 64 + nt * 8 + t4 * 2 + (cr & 1);
            float v = fmaxf(acc[nt][cr] + bias[col], 0.f);
            out[(size_t)(r & ~63) * 128 + xpack_off(r & 63, col)] = __float2half_rn(v);
        }
}

// ---------------- persistent fused LSTM (fp16 mma, barrier-free chunks) ----------------
// Smem bytes: Bs 16 warps x 4 slots x 1KB = 65536 | Xs 2 x 16KB = 32768 | Hs 16384 | bias 2048
#define OFFB_XS   65536
#define OFFB_HS   98304
#define OFFB_BIAS 114688
#define SMEM_BYTES (114688 + 2048)

__global__ void __launch_bounds__(512, 1) k_lstm(const __half* __restrict__ enc,
                                                 const __half* __restrict__ Wp,
                                                 const float* __restrict__ bih,
                                                 const float* __restrict__ bhh,
                                                 __half* __restrict__ Xa,
                                                 __half* __restrict__ Xb) {
    extern __shared__ __align__(16) unsigned char smraw[];
    __half* Bsh = (__half*)smraw;
    __half* Xsb = (__half*)(smraw + OFFB_XS);
    __half* Hs  = (__half*)(smraw + OFFB_HS);
    float*  bs  = (float*)(smraw + OFFB_BIAS);

    const int tid  = threadIdx.x;
    const int lane = tid & 31;
    const int w    = tid >> 5;
    const int g    = lane >> 2;
    const int t4   = lane & 3;
    const int gidx = g * 4 + t4;
    const int gsw  = g & 1;
    const int row0 = blockIdx.x * 64;
    __half* Bw = Bsh + w * 2048;              // warp-private 4-slot region (4 x 512h)

    float creg[16];
#pragma unroll
    for (int i = 0; i < 16; i++) creg[i] = 0.f;

    // ---- init ----
    bs[tid] = bih[tid] + bhh[tid];
#pragma unroll
    for (int i = 0; i < 2; i++) {             // Xs[0] <- enc tile (linear, already packed)
        int idx = i * 512 + tid;              // uint4 index over 8192 halfs
        *(uint4*)&Xsb[idx * 8] = *(const uint4*)&enc[(size_t)row0 * 128 + idx * 8];
    }
    __syncthreads();

    auto issueB = [&](int nn) {
        int lq = nn / 184;
        int rq = nn - lq * 184;
        int kcq = (rq < 8) ? rq : ((rq - 8) & 15);
        const __half* src = Wp + (((size_t)(lq * 16 + kcq) * 16 + w) << 9);
        __half* dst = Bw + (nn & 3) * 512;
#pragma unroll
        for (int i = 0; i < 2; i++) {
            int off = i * 256 + lane * 8;
            cp16(dst + off, src + off);
        }
    };
    auto issueX = [&](const __half* srcT, int xb) {   // warp's 1KB slice of next packed tile
#pragma unroll
        for (int i = 0; i < 2; i++) {
            int off = w * 512 + i * 256 + lane * 8;
            cp16(Xsb + xb * 8192 + off, srcT + (size_t)row0 * 128 + off);
        }
    };

    issueB(0); CP_COMMIT();
    issueB(1); CP_COMMIT();
    issueB(2); CP_COMMIT();

    const __half* Xin = Xa;
    __half*       Xout = Xa;
    float acc[4][4][4];
    int n = 0;
    int xbuf = 0;

    for (int l = 0; l < LAYERS; l++) {
        for (int t = 0; t < TT; t++) {
#pragma unroll
            for (int a = 0; a < 4; a++)
#pragma unroll
                for (int b = 0; b < 4; b++)
#pragma unroll
                    for (int q = 0; q < 4; q++) acc[a][b][q] = 0.f;

            const int nkc  = (t == 0) ? 8 : 16;
            const int trig = (t == 0) ? 3 : 7;
            const bool needX = (t < TT - 1) ? (l > 0) : (l < LAYERS - 1);
            const __half* xsrc = (t < TT - 1) ? (Xin + (size_t)(t + 1) * BATCH * 128) : Xout;

            for (int kc = 0; kc < nkc; kc++) {
                CP_WAIT(2);                           // warp-private: slot n&3 landed
                const __half* Bb   = Bw + (n & 3) * 512;
                const __half* Asrc = (kc < 8) ? (Xsb + xbuf * 8192 + kc * 1024)
                                              : (Hs + (kc - 8) * 1024);
                uint4 Af[4];
#pragma unroll
                for (int mf = 0; mf < 4; mf++)
                    Af[mf] = *(const uint4*)&Asrc[mf * 256 + gidx * 8];
                unsigned b0[4], b1[4];
#pragma unroll
                for (int P = 0; P < 2; P++) {
                    uint4 Bv = *(const uint4*)&Bb[gidx * 16 + (P ^ gsw) * 8];
                    b0[P * 2] = Bv.x;  b1[P * 2] = Bv.y;
                    b0[P * 2 + 1] = Bv.z;  b1[P * 2 + 1] = Bv.w;
                }
#pragma unroll
                for (int gt = 0; gt < 4; gt++)
#pragma unroll
                    for (int mf = 0; mf < 4; mf++)
                        mma_f16(acc[mf][gt], Af[mf].x, Af[mf].y, Af[mf].z, Af[mf].w,
                                b0[gt], b1[gt]);

                if (kc == trig && needX) { issueX(xsrc, xbuf ^ 1); CP_COMMIT(); }
                int gn = n + 3;
                if (gn < NCHUNK_TOTAL) { issueB(gn); CP_COMMIT(); }
                n++;
            }

            // ---- cell epilogue: 4 gates + c in registers, emit packed h ----
            __syncthreads();                     // all warps done reading Hs this step
#pragma unroll
            for (int mf = 0; mf < 4; mf++) {
                __half hv[4];
#pragma unroll
                for (int q = 0; q < 2; q++)
#pragma unroll
                    for (int d = 0; d < 2; d++) {
                        int cr = q * 2 + d;
                        int j  = w * 8 + t4 * 2 + d;
                        float gi = acc[mf][0][cr] + bs[j];
                        float gf = acc[mf][1][cr] + bs[128 + j];
                        float gg = acc[mf][2][cr] + bs[256 + j];
                        float go = acc[mf][3][cr] + bs[384 + j];
                        int ci = mf * 4 + q * 2 + d;
                        float cn = sigf(gf) * creg[ci] + sigf(gi) * tanh_fast(gg);
                        float h  = sigf(go) * tanh_fast(cn);
                        creg[ci] = cn;
                        hv[q * 2 + d] = __float2half_rn(h);
                    }
                // one STS.64 per m-frag into the packed Hs granule (this warp's kh half)
                *(uint2*)&Hs[(w >> 1) * 1024 + mf * 256 + gidx * 8 + (w & 1) * 4] =
                    *(const uint2*)hv;
            }
            __syncthreads();                     // Hs complete
            // coalesced packed h -> global
#pragma unroll
            for (int i = 0; i < 2; i++) {
                int idx = i * 512 + tid;
                *(uint4*)&Xout[((size_t)t * BATCH + row0) * 128 + idx * 8] =
                    *(const uint4*)&Hs[idx * 8];
            }
            if (t == TT - 1 && l + 1 < LAYERS) {
                bs[tid] = bih[(l + 1) * 512 + tid] + bhh[(l + 1) * 512 + tid];
#pragma unroll
                for (int i = 0; i < 16; i++) creg[i] = 0.f;
            }
            if (needX) xbuf ^= 1;
        }
        Xin  = Xout;
        Xout = (Xout == Xa) ? Xb : Xa;
    }
    CP_WAIT(0);
}

// ---------------- fc_out: packed-fp16 Y @ W^T + b, fused scatter ----------------
__global__ void __launch_bounds__(256) k_fcout(const __half* __restrict__ Y,
                                               const float* __restrict__ W,
                                               const float* __restrict__ bias,
                                               float* __restrict__ pred,
                                               float* __restrict__ plog) {
    __shared__ __half As[2048];      // 2 tiles x 1024 halfs (one chunk slice)
    __shared__ __half Bsm[80 * 16];  // [n][k] halfs
    const int tid  = threadIdx.x;
    const int lane = tid & 31;
    const int wm   = tid >> 5;       // 8 warps: tile = wm>>2, mf = wm&3
    const int row0 = blockIdx.x * 128;
    const int g    = lane >> 2;
    const int t4   = lane & 3;
    const int gidx = g * 4 + t4;

    float acc[10][4];
#pragma unroll
    for (int i = 0; i < 10; i++)
#pragma unroll
        for (int j = 0; j < 4; j++) acc[i][j] = 0.f;

    for (int kc = 0; kc < 8; kc++) {
        // A: linear copy of this chunk's packed slice (2 tiles x 1024 halfs)
        {
            int tilei = tid >> 7, rest = tid & 127;
            *(uint4*)&As[tid * 8] =
                *(const uint4*)&Y[(size_t)(row0 + tilei * 64) * 128 + kc * 1024 + rest * 8];
        }
        // B: f32 -> f16, [n][k] (rows >= 75 zero)
#pragma unroll
        for (int i = 0; i < 5; i++) {
            int idx = tid + i * 256;
            int c = idx >> 4, kl = idx & 15;
            float v = (c < 75) ? W[(size_t)c * 128 + kc * 16 + kl] : 0.f;
            Bsm[c * 16 + kl] = __float2half_rn(v);
        }
        __syncthreads();
        uint4 Av = *(const uint4*)&As[(wm >> 2) * 1024 + (wm & 3) * 256 + gidx * 8];
#pragma unroll
        for (int nt = 0; nt < 10; nt++) {
            int col = nt * 8 + g;
            unsigned b0 = *(const unsigned*)&Bsm[col * 16 + t4 * 2];
            unsigned b1 = *(const unsigned*)&Bsm[col * 16 + 8 + t4 * 2];
            mma_f16(acc[nt], Av.x, Av.y, Av.z, Av.w, b0, b1);
        }
        __syncthreads();
    }
#pragma unroll
    for (int nt = 0; nt < 10; nt++)
#pragma unroll
        for (int cr = 0; cr < 4; cr++) {
            int col = nt * 8 + t4 * 2 + (cr & 1);
            if (col >= 75) continue;
            int r = row0 + wm * 16 + g + (cr >> 1) * 8;
            int t = r >> 13;
            int b = r & (BATCH - 1);
            float v = acc[nt][cr] + bias[col];
            if (col < 50) {
                int m = col >> 1, d = col & 1;
                pred[b * (NMODES * TT * 2) + m * (TT * 2) + t * 2 + d] = v;
            } else if (t == TT - 1) {
                plog[b * NMODES + (col - 50)] = v;
            }
        }
}

// ---------------- softmax over 25 modes ----------------
__global__ void __launch_bounds__(256) k_softmax(const float* __restrict__ plog,
                                                 float* __restrict__ out) {
    int b = blockIdx.x * blockDim.x + threadIdx.x;
    if (b >= BATCH) return;
    float v[NMODES];
    float m = -1e30f;
#pragma unroll
    for (int j = 0; j < NMODES; j++) {
        v[j] = plog[b * NMODES + j];
        m = fmaxf(m, v[j]);
    }
    float s = 0.f;
#pragma unroll
    for (int j = 0; j < NMODES; j++) {
        v[j] = __expf(v[j] - m);
        s += v[j];
    }
    float inv = __fdividef(1.f, s);
#pragma unroll
    for (int j = 0; j < NMODES; j++) out[b * NMODES + j] = v[j] * inv;
}

// ---------------- launcher ----------------
extern "C" void kernel_launch(void* const* d_in, const int* in_sizes, int n_in,
                              void* d_out, int out_size) {
    const float* backbone = (const float*)d_in[0];
    const float* fcW      = (const float*)d_in[1];
    const float* fcb      = (const float*)d_in[2];
    const float* Wih      = (const float*)d_in[3];
    const float* Whh      = (const float*)d_in[4];
    const float* bih      = (const float*)d_in[5];
    const float* bhh      = (const float*)d_in[6];
    const float* foW      = (const float*)d_in[7];
    const float* fob      = (const float*)d_in[8];

    float* out  = (float*)d_out;
    float* pred = out;
    float* prob = out + (size_t)BATCH * NMODES * TT * 2;

    __half *encp, *pXa, *pXb, *wp;
    float* plogb;
    cudaGetSymbolAddress((void**)&encp,  g_encp);
    cudaGetSymbolAddress((void**)&pXa,   g_Xa);
    cudaGetSymbolAddress((void**)&pXb,   g_Xb);
    cudaGetSymbolAddress((void**)&wp,    g_Wp);
    cudaGetSymbolAddress((void**)&plogb, g_plog);

    cudaFuncSetAttribute(k_lstm, cudaFuncAttributeMaxDynamicSharedMemorySize, SMEM_BYTES);

    k_pack<<<(LAYERS * 16 * 16 * 512 + 255) / 256, 256>>>(Wih, Whh, wp);
    k_fcin<<<BATCH / 64, 256>>>(backbone, fcW, fcb, encp);
    k_lstm<<<BATCH / 64, 512, SMEM_BYTES>>>(encp, wp, bih, bhh, pXa, pXb);
    // LAYERS = 10 (even): final output lives in g_Xb
    k_fcout<<<(TT * BATCH) / 128, 256>>>(pXb, foW, fob, pred, plogb);
    k_softmax<<<BATCH / 256, 256>>>(plogb, prob);
}

// round 15
// speedup vs baseline: 4.2059x; 1.0068x over previous
#include <cuda_runtime.h>
#include <cuda_fp16.h>

#define BATCH   8192
#define HID     128
#define TT      12
#define LAYERS  10
#define G4      512
#define ENCL    4096
#define NMODES  25

#define NCHUNK_TOTAL 1840   // per layer: 8 (t=0) + 11*16

// ---------------- scratch (static device globals; no allocation) ----------------
__device__ __half g_encp[BATCH * HID];                  // enc, fp16, fragment-packed
__device__ __half g_Xa  [TT * BATCH * HID];             // inter-layer x (fp16, packed)
__device__ __half g_Xb  [TT * BATCH * HID];
__device__ __half g_Wp  [LAYERS * 16 * 16 * 512];       // packed fp16 weights [l][kc][w][512h]
__device__ float  g_plog[BATCH * NMODES];

// ---------------- helpers ----------------
__device__ __forceinline__ unsigned f2tf(float x) {
    unsigned u;
    asm("cvt.rna.tf32.f32 %0, %1;" : "=r"(u) : "f"(x));
    return u;
}
__device__ __forceinline__ void mma_tf32(float c[4],
                                         unsigned a0, unsigned a1, unsigned a2, unsigned a3,
                                         unsigned b0, unsigned b1) {
    asm volatile(
        "mma.sync.aligned.m16n8k8.row.col.f32.tf32.tf32.f32 "
        "{%0,%1,%2,%3}, {%4,%5,%6,%7}, {%8,%9}, {%0,%1,%2,%3};\n"
        : "+f"(c[0]), "+f"(c[1]), "+f"(c[2]), "+f"(c[3])
        : "r"(a0), "r"(a1), "r"(a2), "r"(a3), "r"(b0), "r"(b1));
}
__device__ __forceinline__ void mma_f16(float c[4],
                                        unsigned a0, unsigned a1, unsigned a2, unsigned a3,
                                        unsigned b0, unsigned b1) {
    asm volatile(
        "mma.sync.aligned.m16n8k16.row.col.f32.f16.f16.f32 "
        "{%0,%1,%2,%3}, {%4,%5,%6,%7}, {%8,%9}, {%0,%1,%2,%3};\n"
        : "+f"(c[0]), "+f"(c[1]), "+f"(c[2]), "+f"(c[3])
        : "r"(a0), "r"(a1), "r"(a2), "r"(a3), "r"(b0), "r"(b1));
}
__device__ __forceinline__ float sigf(float x) { return __fdividef(1.f, 1.f + __expf(-x)); }
__device__ __forceinline__ float tanh_fast(float x) { return __fdividef(2.f, 1.f + __expf(-2.f * x)) - 1.f; }

__device__ __forceinline__ void cp16(void* dst_smem, const void* src) {
    unsigned d = (unsigned)__cvta_generic_to_shared(dst_smem);
    asm volatile("cp.async.cg.shared.global [%0], [%1], 16;\n" :: "r"(d), "l"(src));
}
#define CP_COMMIT() asm volatile("cp.async.commit_group;\n" ::: "memory")
#define CP_WAIT(N)  asm volatile("cp.async.wait_group %0;\n" :: "n"(N) : "memory")

// ======================= fragment-packed fp16 layouts =======================
// X/H tile (64 rows x 128 cols), 8192 halfs per tile:
//   off_h = c*1024 + mf*256 + (g*4+t4)*8 + kh*4 + q*2 + d
//   where c=col>>4, t4=(col>>1)&3, kh=(col>>3)&1, d=col&1, mf=r>>4, q=(r>>3)&1, g=r&7.
//   One LDS.128 at (mf*256 + gidx*8) yields mma A regs [a0,a1,a2,a3].
// B (weights) per (l,kc,warp): 512 halfs:
//   off_h = gidx*16 + (P ^ (g&1))*8 + (gt&1)*4 + kh*2 + d    (gidx=g*4+t4, P=gt>>1)
//   One LDS.128 at (gidx*16 + (P^(g&1))*8) yields [b0(2P),b1(2P),b0(2P+1),b1(2P+1)].

__device__ __forceinline__ int xpack_off(int r6, int col) {   // r6 in [0,64), col in [0,128)
    int c = col >> 4, t4 = (col >> 1) & 3, kh = (col >> 3) & 1, d = col & 1;
    int mf = r6 >> 4, q = (r6 >> 3) & 1, g = r6 & 7;
    return c * 1024 + mf * 256 + (g * 4 + t4) * 8 + kh * 4 + q * 2 + d;
}

// ---------------- weight pre-pack ----------------
__global__ void __launch_bounds__(256) k_pack(const float* __restrict__ Wih,
                                              const float* __restrict__ Whh,
                                              __half* __restrict__ Wp) {
    int idx = blockIdx.x * 256 + threadIdx.x;
    if (idx >= LAYERS * 16 * 16 * 512) return;
    int hoff = idx & 511;
    int w    = (idx >> 9) & 15;
    int kc   = (idx >> 13) & 15;
    int l    = idx >> 17;
    int gidx = hoff >> 4, rem = hoff & 15;
    int g = gidx >> 2, t4 = gidx & 3;
    int seg = rem >> 3;
    int P = seg ^ (g & 1);
    int gt = P * 2 + ((rem >> 2) & 1);
    int kh = (rem >> 1) & 1, d = rem & 1;
    int col = gt * 128 + w * 8 + g;
    int kk  = (kc & 7) * 16 + kh * 8 + t4 * 2 + d;
    float v = (kc < 8) ? Wih[((size_t)l * 512 + col) * 128 + kk]
                       : Whh[((size_t)l * 512 + col) * 128 + kk];
    Wp[idx] = __float2half_rn(v);
}

// ---------------- fc_in: enc = fp16pack(relu(backbone @ W^T + b)), tf32 core ----------------
__global__ void __launch_bounds__(256) k_fcin(const float* __restrict__ A,
                                              const float* __restrict__ W,
                                              const float* __restrict__ bias,
                                              __half* __restrict__ out) {
    __shared__ unsigned smf[3 * 3840];          // per buf: As 64*20, Bs 128*20
    const int tid  = threadIdx.x;
    const int lane = tid & 31;
    const int w    = tid >> 5;
    const int wm   = w & 3;
    const int wn   = w >> 2;
    const int row0 = blockIdx.x * 64;
    const int g    = lane >> 2;
    const int t4   = lane & 3;

    float acc[8][4];
#pragma unroll
    for (int i = 0; i < 8; i++)
#pragma unroll
        for (int j = 0; j < 4; j++) acc[i][j] = 0.f;

    auto issue = [&](int kc) {
        unsigned* As = smf + (kc % 3) * 3840;
        unsigned* Bs = As + 1280;
        const int k0 = kc * 16;
        {
            int m = tid >> 2, kv = tid & 3;
            cp16(As + m * 20 + kv * 4, A + (size_t)(row0 + m) * ENCL + k0 + kv * 4);
        }
#pragma unroll
        for (int i = 0; i < 2; i++) {
            int idx = tid + i * 256;
            int n = idx >> 2, kv = idx & 3;
            cp16(Bs + n * 20 + kv * 4, W + (size_t)n * ENCL + k0 + kv * 4);
        }
    };

    issue(0); CP_COMMIT();
    issue(1); CP_COMMIT();

    for (int kc = 0; kc < ENCL / 16; kc++) {
        CP_WAIT(1);
        __syncthreads();
        if (kc + 2 < ENCL / 16) issue(kc + 2);
        CP_COMMIT();
        const unsigned* As = smf + (kc % 3) * 3840;
        const unsigned* Bs = As + 1280;
#pragma unroll
        for (int ks = 0; ks < 2; ks++) {
            const int kb = ks * 8;
            unsigned a0 = As[(wm * 16 + g) * 20 + kb + t4];
            unsigned a1 = As[(wm * 16 + g + 8) * 20 + kb + t4];
            unsigned a2 = As[(wm * 16 + g) * 20 + kb + t4 + 4];
            unsigned a3 = As[(wm * 16 + g + 8) * 20 + kb + t4 + 4];
#pragma unroll
            for (int nt = 0; nt < 8; nt++) {
                int col = wn * 64 + nt * 8 + g;
                unsigned b0 = Bs[col * 20 + kb + t4];
                unsigned b1 = Bs[col * 20 + kb + t4 + 4];
                mma_tf32(acc[nt], a0, a1, a2, a3, b0, b1);
            }
        }
    }
#pragma unroll
    for (int nt = 0; nt < 8; nt++)
#pragma unroll
        for (int cr = 0; cr < 4; cr++) {
            int r   = row0 + wm * 16 + g + (cr >> 1) * 8;
            int col = wn * 64 + nt * 8 + t4 * 2 + (cr & 1);
            float v = fmaxf(acc[nt][cr] + bias[col], 0.f);
            out[(size_t)(r & ~63) * 128 + xpack_off(r & 63, col)] = __float2half_rn(v);
        }
}

// ---------------- persistent fused LSTM (fp16 mma, barrier-free chunks) ----------------
// Smem bytes: Bs 16 warps x 4 slots x 1KB = 65536 | Xs 2 x 16KB = 32768 | Hs 16384 | bias 2048
#define OFFB_XS   65536
#define OFFB_HS   98304
#define OFFB_BIAS 114688
#define SMEM_BYTES (114688 + 2048)

__global__ void __launch_bounds__(512, 1) k_lstm(const __half* __restrict__ enc,
                                                 const __half* __restrict__ Wp,
                                                 const float* __restrict__ bih,
                                                 const float* __restrict__ bhh,
                                                 __half* __restrict__ Xa,
                                                 __half* __restrict__ Xb) {
    extern __shared__ __align__(16) unsigned char smraw[];
    __half* Bsh = (__half*)smraw;
    __half* Xsb = (__half*)(smraw + OFFB_XS);
    __half* Hs  = (__half*)(smraw + OFFB_HS);
    float*  bs  = (float*)(smraw + OFFB_BIAS);

    const int tid  = threadIdx.x;
    const int lane = tid & 31;
    const int w    = tid >> 5;
    const int g    = lane >> 2;
    const int t4   = lane & 3;
    const int gidx = g * 4 + t4;
    const int gsw  = g & 1;
    const int row0 = blockIdx.x * 64;
    __half* Bw = Bsh + w * 2048;              // warp-private 4-slot region (4 x 512h)

    float creg[16];
#pragma unroll
    for (int i = 0; i < 16; i++) creg[i] = 0.f;

    // ---- init ----
    bs[tid] = bih[tid] + bhh[tid];
#pragma unroll
    for (int i = 0; i < 2; i++) {             // Xs[0] <- enc tile (linear, already packed)
        int idx = i * 512 + tid;              // uint4 index over 8192 halfs
        *(uint4*)&Xsb[idx * 8] = *(const uint4*)&enc[(size_t)row0 * 128 + idx * 8];
    }
    __syncthreads();

    auto issueB = [&](int nn) {
        int lq = nn / 184;
        int rq = nn - lq * 184;
        int kcq = (rq < 8) ? rq : ((rq - 8) & 15);
        const __half* src = Wp + (((size_t)(lq * 16 + kcq) * 16 + w) << 9);
        __half* dst = Bw + (nn & 3) * 512;
#pragma unroll
        for (int i = 0; i < 2; i++) {
            int off = i * 256 + lane * 8;
            cp16(dst + off, src + off);
        }
    };
    auto issueX = [&](const __half* srcT, int xb) {   // warp's 1KB slice of next packed tile
#pragma unroll
        for (int i = 0; i < 2; i++) {
            int off = w * 512 + i * 256 + lane * 8;
            cp16(Xsb + xb * 8192 + off, srcT + (size_t)row0 * 128 + off);
        }
    };

    issueB(0); CP_COMMIT();
    issueB(1); CP_COMMIT();
    issueB(2); CP_COMMIT();

    const __half* Xin = Xa;
    __half*       Xout = Xa;
    float acc[4][4][4];
    int n = 0;
    int xbuf = 0;

    for (int l = 0; l < LAYERS; l++) {
        for (int t = 0; t < TT; t++) {
#pragma unroll
            for (int a = 0; a < 4; a++)
#pragma unroll
                for (int b = 0; b < 4; b++)
#pragma unroll
                    for (int q = 0; q < 4; q++) acc[a][b][q] = 0.f;

            const int nkc  = (t == 0) ? 8 : 16;
            const int trig = (t == 0) ? 3 : 7;
            const bool needX = (t < TT - 1) ? (l > 0) : (l < LAYERS - 1);
            const __half* xsrc = (t < TT - 1) ? (Xin + (size_t)(t + 1) * BATCH * 128) : Xout;

            for (int kc = 0; kc < nkc; kc++) {
                CP_WAIT(2);                           // warp-private: slot n&3 landed
                const __half* Bb   = Bw + (n & 3) * 512;
                const __half* Asrc = (kc < 8) ? (Xsb + xbuf * 8192 + kc * 1024)
                                              : (Hs + (kc - 8) * 1024);
                uint4 Af[4];
#pragma unroll
                for (int mf = 0; mf < 4; mf++)
                    Af[mf] = *(const uint4*)&Asrc[mf * 256 + gidx * 8];
                unsigned b0[4], b1[4];
#pragma unroll
                for (int P = 0; P < 2; P++) {
                    uint4 Bv = *(const uint4*)&Bb[gidx * 16 + (P ^ gsw) * 8];
                    b0[P * 2] = Bv.x;  b1[P * 2] = Bv.y;
                    b0[P * 2 + 1] = Bv.z;  b1[P * 2 + 1] = Bv.w;
                }
#pragma unroll
                for (int gt = 0; gt < 4; gt++)
#pragma unroll
                    for (int mf = 0; mf < 4; mf++)
                        mma_f16(acc[mf][gt], Af[mf].x, Af[mf].y, Af[mf].z, Af[mf].w,
                                b0[gt], b1[gt]);

                if (kc == trig && needX) { issueX(xsrc, xbuf ^ 1); CP_COMMIT(); }
                int gn = n + 3;
                if (gn < NCHUNK_TOTAL) { issueB(gn); CP_COMMIT(); }
                n++;
            }

            // ---- cell epilogue: 4 gates + c in registers, emit packed h ----
            __syncthreads();                     // all warps done reading Hs this step
#pragma unroll
            for (int mf = 0; mf < 4; mf++) {
                __half hv[4];
#pragma unroll
                for (int q = 0; q < 2; q++)
#pragma unroll
                    for (int d = 0; d < 2; d++) {
                        int cr = q * 2 + d;
                        int j  = w * 8 + t4 * 2 + d;
                        float gi = acc[mf][0][cr] + bs[j];
                        float gf = acc[mf][1][cr] + bs[128 + j];
                        float gg = acc[mf][2][cr] + bs[256 + j];
                        float go = acc[mf][3][cr] + bs[384 + j];
                        int ci = mf * 4 + q * 2 + d;
                        float cn = sigf(gf) * creg[ci] + sigf(gi) * tanh_fast(gg);
                        float h  = sigf(go) * tanh_fast(cn);
                        creg[ci] = cn;
                        hv[q * 2 + d] = __float2half_rn(h);
                    }
                // one STS.64 per m-frag into the packed Hs granule (this warp's kh half)
                *(uint2*)&Hs[(w >> 1) * 1024 + mf * 256 + gidx * 8 + (w & 1) * 4] =
                    *(const uint2*)hv;
            }
            __syncthreads();                     // Hs complete
            // coalesced packed h -> global
#pragma unroll
            for (int i = 0; i < 2; i++) {
                int idx = i * 512 + tid;
                *(uint4*)&Xout[((size_t)t * BATCH + row0) * 128 + idx * 8] =
                    *(const uint4*)&Hs[idx * 8];
            }
            if (t == TT - 1 && l + 1 < LAYERS) {
                bs[tid] = bih[(l + 1) * 512 + tid] + bhh[(l + 1) * 512 + tid];
#pragma unroll
                for (int i = 0; i < 16; i++) creg[i] = 0.f;
            }
            if (needX) xbuf ^= 1;
        }
        Xin  = Xout;
        Xout = (Xout == Xa) ? Xb : Xa;
    }
    CP_WAIT(0);
}

// ---------------- fc_out: packed-fp16 Y @ W^T + b, fused scatter ----------------
__global__ void __launch_bounds__(256) k_fcout(const __half* __restrict__ Y,
                                               const float* __restrict__ W,
                                               const float* __restrict__ bias,
                                               float* __restrict__ pred,
                                               float* __restrict__ plog) {
    __shared__ __half As[2048];      // 2 tiles x 1024 halfs (one chunk slice)
    __shared__ __half Bsm[80 * 16];  // [n][k] halfs
    const int tid  = threadIdx.x;
    const int lane = tid & 31;
    const int wm   = tid >> 5;       // 8 warps: tile = wm>>2, mf = wm&3
    const int row0 = blockIdx.x * 128;
    const int g    = lane >> 2;
    const int t4   = lane & 3;
    const int gidx = g * 4 + t4;

    float acc[10][4];
#pragma unroll
    for (int i = 0; i < 10; i++)
#pragma unroll
        for (int j = 0; j < 4; j++) acc[i][j] = 0.f;

    for (int kc = 0; kc < 8; kc++) {
        // A: linear copy of this chunk's packed slice (2 tiles x 1024 halfs)
        {
            int tilei = tid >> 7, rest = tid & 127;
            *(uint4*)&As[tid * 8] =
                *(const uint4*)&Y[(size_t)(row0 + tilei * 64) * 128 + kc * 1024 + rest * 8];
        }
        // B: f32 -> f16, [n][k] (rows >= 75 zero)
#pragma unroll
        for (int i = 0; i < 5; i++) {
            int idx = tid + i * 256;
            int c = idx >> 4, kl = idx & 15;
            float v = (c < 75) ? W[(size_t)c * 128 + kc * 16 + kl] : 0.f;
            Bsm[c * 16 + kl] = __float2half_rn(v);
        }
        __syncthreads();
        uint4 Av = *(const uint4*)&As[(wm >> 2) * 1024 + (wm & 3) * 256 + gidx * 8];
#pragma unroll
        for (int nt = 0; nt < 10; nt++) {
            int col = nt * 8 + g;
            unsigned b0 = *(const unsigned*)&Bsm[col * 16 + t4 * 2];
            unsigned b1 = *(const unsigned*)&Bsm[col * 16 + 8 + t4 * 2];
            mma_f16(acc[nt], Av.x, Av.y, Av.z, Av.w, b0, b1);
        }
        __syncthreads();
    }
#pragma unroll
    for (int nt = 0; nt < 10; nt++)
#pragma unroll
        for (int cr = 0; cr < 4; cr++) {
            int col = nt * 8 + t4 * 2 + (cr & 1);
            if (col >= 75) continue;
            int r = row0 + wm * 16 + g + (cr >> 1) * 8;
            int t = r >> 13;
            int b = r & (BATCH - 1);
            float v = acc[nt][cr] + bias[col];
            if (col < 50) {
                int m = col >> 1, d = col & 1;
                pred[b * (NMODES * TT * 2) + m * (TT * 2) + t * 2 + d] = v;
            } else if (t == TT - 1) {
                plog[b * NMODES + (col - 50)] = v;
            }
        }
}

// ---------------- softmax over 25 modes ----------------
__global__ void __launch_bounds__(256) k_softmax(const float* __restrict__ plog,
                                                 float* __restrict__ out) {
    int b = blockIdx.x * blockDim.x + threadIdx.x;
    if (b >= BATCH) return;
    float v[NMODES];
    float m = -1e30f;
#pragma unroll
    for (int j = 0; j < NMODES; j++) {
        v[j] = plog[b * NMODES + j];
        m = fmaxf(m, v[j]);
    }
    float s = 0.f;
#pragma unroll
    for (int j = 0; j < NMODES; j++) {
        v[j] = __expf(v[j] - m);
        s += v[j];
    }
    float inv = __fdividef(1.f, s);
#pragma unroll
    for (int j = 0; j < NMODES; j++) out[b * NMODES + j] = v[j] * inv;
}

// ---------------- launcher ----------------
extern "C" void kernel_launch(void* const* d_in, const int* in_sizes, int n_in,
                              void* d_out, int out_size) {
    const float* backbone = (const float*)d_in[0];
    const float* fcW      = (const float*)d_in[1];
    const float* fcb      = (const float*)d_in[2];
    const float* Wih      = (const float*)d_in[3];
    const float* Whh      = (const float*)d_in[4];
    const float* bih      = (const float*)d_in[5];
    const float* bhh      = (const float*)d_in[6];
    const float* foW      = (const float*)d_in[7];
    const float* fob      = (const float*)d_in[8];

    float* out  = (float*)d_out;
    float* pred = out;
    float* prob = out + (size_t)BATCH * NMODES * TT * 2;

    __half *encp, *pXa, *pXb, *wp;
    float* plogb;
    cudaGetSymbolAddress((void**)&encp,  g_encp);
    cudaGetSymbolAddress((void**)&pXa,   g_Xa);
    cudaGetSymbolAddress((void**)&pXb,   g_Xb);
    cudaGetSymbolAddress((void**)&wp,    g_Wp);
    cudaGetSymbolAddress((void**)&plogb, g_plog);

    cudaFuncSetAttribute(k_lstm, cudaFuncAttributeMaxDynamicSharedMemorySize, SMEM_BYTES);

    k_pack<<<(LAYERS * 16 * 16 * 512 + 255) / 256, 256>>>(Wih, Whh, wp);
    k_fcin<<<BATCH / 64, 256>>>(backbone, fcW, fcb, encp);
    k_lstm<<<BATCH / 64, 512, SMEM_BYTES>>>(encp, wp, bih, bhh, pXa, pXb);
    // LAYERS = 10 (even): final output lives in g_Xb
    k_fcout<<<(TT * BATCH) / 128, 256>>>(pXb, foW, fob, pred, plogb);
    k_softmax<<<BATCH / 256, 256>>>(plogb, prob);
}